// round 2
// baseline (speedup 1.0000x reference)
#include <cuda_runtime.h>
#include <math.h>

#define N_GRAPHS 4096
#define NODE_SIZE 512
#define GLOBAL_SIZE 256
#define HIDDEN_SIZE 1024
#define INPUT_SIZE 768   // GLOBAL_SIZE + NODE_SIZE

// ---------------- scratch (static device globals; no allocation) ------------
__device__ float g_sums[N_GRAPHS * NODE_SIZE];   // 8 MB
__device__ float g_cnt [N_GRAPHS];
__device__ float g_in  [N_GRAPHS * INPUT_SIZE];  // 12.6 MB
__device__ float g_h   [N_GRAPHS * HIDDEN_SIZE]; // 16 MB

// ---------------- kernel 0: zero the accumulators ---------------------------
__global__ void zero_kernel() {
    int stride = gridDim.x * blockDim.x;
    int tid = blockIdx.x * blockDim.x + threadIdx.x;
    for (int i = tid; i < N_GRAPHS * NODE_SIZE; i += stride) g_sums[i] = 0.f;
    for (int i = tid; i < N_GRAPHS;             i += stride) g_cnt[i]  = 0.f;
}

// ---------------- kernel 1: sorted segment reduction ------------------------
// batch is sorted ascending (int32 — JAX x64 is off, "int64" arrays are int32).
// Each block owns a contiguous row chunk; threads accumulate one float4 column
// slice in registers and flush with atomics only when the graph id changes
// (~122 nodes/graph -> ~1-2 flushes per 128-row chunk).
constexpr int ROWS_PER_BLOCK = 128;

__global__ __launch_bounds__(128) void seg_reduce(
    const float* __restrict__ x, const int* __restrict__ batch, int n)
{
    int r0 = blockIdx.x * ROWS_PER_BLOCK;
    int r1 = min(r0 + ROWS_PER_BLOCK, n);
    if (r0 >= r1) return;

    const int c = threadIdx.x * 4;          // 128 threads * 4 = 512 cols
    float4 acc = make_float4(0.f, 0.f, 0.f, 0.f);
    float  cnt = 0.f;
    int cur = min(max(batch[r0], 0), N_GRAPHS - 1);

    for (int r = r0; r < r1; ++r) {
        int b = min(max(__ldg(&batch[r]), 0), N_GRAPHS - 1);
        if (b != cur) {
            float* dst = &g_sums[(size_t)cur * NODE_SIZE + c];
            atomicAdd(dst + 0, acc.x); atomicAdd(dst + 1, acc.y);
            atomicAdd(dst + 2, acc.z); atomicAdd(dst + 3, acc.w);
            if (threadIdx.x == 0) atomicAdd(&g_cnt[cur], cnt);
            acc = make_float4(0.f, 0.f, 0.f, 0.f);
            cnt = 0.f;
            cur = b;
        }
        float4 v = *reinterpret_cast<const float4*>(x + (size_t)r * NODE_SIZE + c);
        acc.x += v.x; acc.y += v.y; acc.z += v.z; acc.w += v.w;
        cnt += 1.f;
    }
    float* dst = &g_sums[(size_t)cur * NODE_SIZE + c];
    atomicAdd(dst + 0, acc.x); atomicAdd(dst + 1, acc.y);
    atomicAdd(dst + 2, acc.z); atomicAdd(dst + 3, acc.w);
    if (threadIdx.x == 0) atomicAdd(&g_cnt[cur], cnt);
}

// ---------------- kernel 2: build concat([u, mean]) -------------------------
__global__ __launch_bounds__(192) void prep_kernel(const float* __restrict__ u) {
    int g = blockIdx.x;
    float inv = 1.f / fmaxf(g_cnt[g], 1.f);
    int c = threadIdx.x * 4;                 // 192 threads * 4 = 768 cols
    float4 v;
    if (c < GLOBAL_SIZE) {
        v = *reinterpret_cast<const float4*>(u + (size_t)g * GLOBAL_SIZE + c);
    } else {
        float4 s = *reinterpret_cast<const float4*>(
            &g_sums[(size_t)g * NODE_SIZE + (c - GLOBAL_SIZE)]);
        v = make_float4(s.x * inv, s.y * inv, s.z * inv, s.w * inv);
    }
    *reinterpret_cast<float4*>(&g_in[(size_t)g * INPUT_SIZE + c]) = v;
}

// ---------------- SELU -------------------------------------------------------
__device__ __forceinline__ float selu_f(float v) {
    const float scale = 1.0507009873554805f;
    const float alpha = 1.6732632423543772f;
    return v > 0.f ? scale * v : scale * alpha * (expf(v) - 1.f);
}

// ---------------- register-tiled FP32 GEMM: C = act(A*B + bias) -------------
// A: [M,K] row-major, B: [K,N] row-major, bias: [N]
template <int BM, int BN, int BK, int TM, int TN, bool ACT>
__global__ void __launch_bounds__(256) sgemm_kernel(
    const float* __restrict__ A, const float* __restrict__ B,
    const float* __restrict__ bias, float* __restrict__ C,
    int M, int N, int K)
{
    constexpr int NT = (BM / TM) * (BN / TN);
    static_assert(NT == 256, "need 256 threads");
    constexpr int A4 = BM * BK / 4 / NT;   // float4 A-loads per thread
    constexpr int B4 = BK * BN / 4 / NT;   // float4 B-loads per thread
    static_assert(A4 >= 1 && B4 >= 1, "");

    __shared__ float As[BK][BM + 4];       // +4 floats keeps 16B alignment, trims store conflicts
    __shared__ float Bs[BK][BN];

    const int tid = threadIdx.x;
    const int tx  = tid % (BN / TN);
    const int ty  = tid / (BN / TN);
    const int bm0 = blockIdx.y * BM;
    const int bn0 = blockIdx.x * BN;

    float acc[TM][TN];
    #pragma unroll
    for (int i = 0; i < TM; ++i)
        #pragma unroll
        for (int j = 0; j < TN; ++j) acc[i][j] = 0.f;

    for (int k0 = 0; k0 < K; k0 += BK) {
        #pragma unroll
        for (int i = 0; i < A4; ++i) {
            int e   = (tid + i * NT) * 4;
            int row = e / BK, col = e % BK;
            float4 v = *reinterpret_cast<const float4*>(
                A + (size_t)(bm0 + row) * K + k0 + col);
            As[col + 0][row] = v.x; As[col + 1][row] = v.y;
            As[col + 2][row] = v.z; As[col + 3][row] = v.w;
        }
        #pragma unroll
        for (int i = 0; i < B4; ++i) {
            int e   = (tid + i * NT) * 4;
            int row = e / BN, col = e % BN;
            *reinterpret_cast<float4*>(&Bs[row][col]) =
                *reinterpret_cast<const float4*>(B + (size_t)(k0 + row) * N + bn0 + col);
        }
        __syncthreads();

        #pragma unroll
        for (int kk = 0; kk < BK; ++kk) {
            float ra[TM], rb[TN];
            #pragma unroll
            for (int i = 0; i < TM; i += 4)
                *reinterpret_cast<float4*>(&ra[i]) =
                    *reinterpret_cast<const float4*>(&As[kk][ty * TM + i]);
            #pragma unroll
            for (int j = 0; j < TN; j += 4)
                *reinterpret_cast<float4*>(&rb[j]) =
                    *reinterpret_cast<const float4*>(&Bs[kk][tx * TN + j]);
            #pragma unroll
            for (int i = 0; i < TM; ++i)
                #pragma unroll
                for (int j = 0; j < TN; ++j)
                    acc[i][j] = fmaf(ra[i], rb[j], acc[i][j]);
        }
        __syncthreads();
    }

    #pragma unroll
    for (int i = 0; i < TM; ++i) {
        int row = bm0 + ty * TM + i;
        #pragma unroll
        for (int j = 0; j < TN; j += 4) {
            int col = bn0 + tx * TN + j;
            float4 o;
            o.x = acc[i][j + 0] + bias[col + 0];
            o.y = acc[i][j + 1] + bias[col + 1];
            o.z = acc[i][j + 2] + bias[col + 2];
            o.w = acc[i][j + 3] + bias[col + 3];
            if (ACT) {
                o.x = selu_f(o.x); o.y = selu_f(o.y);
                o.z = selu_f(o.z); o.w = selu_f(o.w);
            }
            *reinterpret_cast<float4*>(&C[(size_t)row * N + col]) = o;
        }
    }
}

// ---------------- launch -----------------------------------------------------
extern "C" void kernel_launch(void* const* d_in, const int* in_sizes, int n_in,
                              void* d_out, int out_size)
{
    const float* x     = (const float*)d_in[0];
    // d_in[1] = edge_index (unused, int32), d_in[2] = edge_attr (unused)
    const float* u     = (const float*)d_in[3];
    const int*   batch = (const int*)d_in[4];   // JAX x64 off: int64 -> int32
    const float* W1    = (const float*)d_in[5];
    const float* b1    = (const float*)d_in[6];
    const float* W2    = (const float*)d_in[7];
    const float* b2    = (const float*)d_in[8];
    float*       out   = (float*)d_out;

    const int n_nodes = in_sizes[0] / NODE_SIZE;

    void *p_in = nullptr, *p_h = nullptr;
    cudaGetSymbolAddress(&p_in, g_in);
    cudaGetSymbolAddress(&p_h,  g_h);

    zero_kernel<<<1024, 256>>>();

    int nblk = (n_nodes + ROWS_PER_BLOCK - 1) / ROWS_PER_BLOCK;
    seg_reduce<<<nblk, 128>>>(x, batch, n_nodes);

    prep_kernel<<<N_GRAPHS, 192>>>(u);

    // GEMM1: [4096,768] @ [768,1024] + b1, SELU -> g_h
    sgemm_kernel<128, 64, 16, 8, 4, true>
        <<<dim3(HIDDEN_SIZE / 64, N_GRAPHS / 128), 256>>>(
            (const float*)p_in, W1, b1, (float*)p_h,
            N_GRAPHS, HIDDEN_SIZE, INPUT_SIZE);

    // GEMM2: [4096,1024] @ [1024,256] + b2 -> out
    sgemm_kernel<64, 64, 16, 4, 4, false>
        <<<dim3(GLOBAL_SIZE / 64, N_GRAPHS / 64), 256>>>(
            (const float*)p_h, W2, b2, out,
            N_GRAPHS, GLOBAL_SIZE, HIDDEN_SIZE);
}

// round 4
// speedup vs baseline: 1.5303x; 1.5303x over previous
#include <cuda_runtime.h>
#include <cuda_bf16.h>
#include <math.h>
#include <stdint.h>

#define N_GRAPHS 4096
#define NODE_SIZE 512
#define GLOBAL_SIZE 256
#define HIDDEN_SIZE 1024
#define INPUT_SIZE 768   // GLOBAL_SIZE + NODE_SIZE

// ---------------- scratch (static device globals; no allocation) ------------
__device__ float g_sums[N_GRAPHS * NODE_SIZE];                 // 8 MB
__device__ float g_cnt [N_GRAPHS];
__device__ __nv_bfloat16 g_a_hi [N_GRAPHS * INPUT_SIZE];       // GEMM1 A split
__device__ __nv_bfloat16 g_a_lo [N_GRAPHS * INPUT_SIZE];
__device__ __nv_bfloat16 g_h_hi [N_GRAPHS * HIDDEN_SIZE];      // GEMM2 A split
__device__ __nv_bfloat16 g_h_lo [N_GRAPHS * HIDDEN_SIZE];
__device__ __nv_bfloat16 g_w1t_hi[HIDDEN_SIZE * INPUT_SIZE];   // W1^T split [N,K]
__device__ __nv_bfloat16 g_w1t_lo[HIDDEN_SIZE * INPUT_SIZE];
__device__ __nv_bfloat16 g_w2t_hi[GLOBAL_SIZE * HIDDEN_SIZE];  // W2^T split [N,K]
__device__ __nv_bfloat16 g_w2t_lo[GLOBAL_SIZE * HIDDEN_SIZE];

// ================= helpers ====================================================
__device__ __forceinline__ uint32_t smem_u32(const void* p) {
    uint32_t a;
    asm("{ .reg .u64 t; cvta.to.shared.u64 t, %1; cvt.u32.u64 %0, t; }"
        : "=r"(a) : "l"(p));
    return a;
}
#define SW128(o) ((o) ^ (((o) >> 3) & 0x70))

__device__ __forceinline__ void ldsm_x4(uint32_t* r, uint32_t addr) {
    asm volatile("ldmatrix.sync.aligned.m8n8.x4.shared.b16 {%0,%1,%2,%3}, [%4];"
                 : "=r"(r[0]), "=r"(r[1]), "=r"(r[2]), "=r"(r[3]) : "r"(addr));
}

__device__ __forceinline__ void mma_bf16(float* c, const uint32_t* a,
                                         const uint32_t* b) {
    asm volatile(
        "mma.sync.aligned.m16n8k16.row.col.f32.bf16.bf16.f32 "
        "{%0,%1,%2,%3}, {%4,%5,%6,%7}, {%8,%9}, {%0,%1,%2,%3};"
        : "+f"(c[0]), "+f"(c[1]), "+f"(c[2]), "+f"(c[3])
        : "r"(a[0]), "r"(a[1]), "r"(a[2]), "r"(a[3]), "r"(b[0]), "r"(b[1]));
}

// ---------------- kernel 0: zero accumulators --------------------------------
__global__ void zero_kernel() {
    int stride = gridDim.x * blockDim.x;
    int tid = blockIdx.x * blockDim.x + threadIdx.x;
    for (int i = tid; i < N_GRAPHS * NODE_SIZE; i += stride) g_sums[i] = 0.f;
    for (int i = tid; i < N_GRAPHS;             i += stride) g_cnt[i]  = 0.f;
}

// ---------------- kernel 1: sorted segment reduction -------------------------
constexpr int ROWS_PER_BLOCK = 128;

__global__ __launch_bounds__(128) void seg_reduce(
    const float* __restrict__ x, const int* __restrict__ batch, int n)
{
    int r0 = blockIdx.x * ROWS_PER_BLOCK;
    int r1 = min(r0 + ROWS_PER_BLOCK, n);
    if (r0 >= r1) return;

    const int c = threadIdx.x * 4;
    float4 acc = make_float4(0.f, 0.f, 0.f, 0.f);
    float  cnt = 0.f;
    int cur = min(max(batch[r0], 0), N_GRAPHS - 1);

    for (int r = r0; r < r1; ++r) {
        int b = min(max(__ldg(&batch[r]), 0), N_GRAPHS - 1);
        if (b != cur) {
            float* dst = &g_sums[(size_t)cur * NODE_SIZE + c];
            atomicAdd(dst + 0, acc.x); atomicAdd(dst + 1, acc.y);
            atomicAdd(dst + 2, acc.z); atomicAdd(dst + 3, acc.w);
            if (threadIdx.x == 0) atomicAdd(&g_cnt[cur], cnt);
            acc = make_float4(0.f, 0.f, 0.f, 0.f);
            cnt = 0.f;
            cur = b;
        }
        float4 v = *reinterpret_cast<const float4*>(x + (size_t)r * NODE_SIZE + c);
        acc.x += v.x; acc.y += v.y; acc.z += v.z; acc.w += v.w;
        cnt += 1.f;
    }
    float* dst = &g_sums[(size_t)cur * NODE_SIZE + c];
    atomicAdd(dst + 0, acc.x); atomicAdd(dst + 1, acc.y);
    atomicAdd(dst + 2, acc.z); atomicAdd(dst + 3, acc.w);
    if (threadIdx.x == 0) atomicAdd(&g_cnt[cur], cnt);
}

// ---------------- bf16 split helpers ------------------------------------------
__device__ __forceinline__ void split_bf16(float v, __nv_bfloat16& h, __nv_bfloat16& l) {
    h = __float2bfloat16(v);
    l = __float2bfloat16(v - __bfloat162float(h));
}

// ---------------- kernel 2: concat([u, mean]) -> bf16 hi/lo ------------------
__global__ __launch_bounds__(192) void prep_split(const float* __restrict__ u) {
    int g = blockIdx.x;
    float inv = 1.f / fmaxf(g_cnt[g], 1.f);
    int c = threadIdx.x * 4;
    float4 v;
    if (c < GLOBAL_SIZE) {
        v = *reinterpret_cast<const float4*>(u + (size_t)g * GLOBAL_SIZE + c);
    } else {
        float4 s = *reinterpret_cast<const float4*>(
            &g_sums[(size_t)g * NODE_SIZE + (c - GLOBAL_SIZE)]);
        v = make_float4(s.x * inv, s.y * inv, s.z * inv, s.w * inv);
    }
    __nv_bfloat16 hx, hy, hz, hw, lx, ly, lz, lw;
    split_bf16(v.x, hx, lx); split_bf16(v.y, hy, ly);
    split_bf16(v.z, hz, lz); split_bf16(v.w, hw, lw);
    size_t o = (size_t)g * INPUT_SIZE + c;
    *reinterpret_cast<__nv_bfloat162*>(&g_a_hi[o])     = __nv_bfloat162(hx, hy);
    *reinterpret_cast<__nv_bfloat162*>(&g_a_hi[o + 2]) = __nv_bfloat162(hz, hw);
    *reinterpret_cast<__nv_bfloat162*>(&g_a_lo[o])     = __nv_bfloat162(lx, ly);
    *reinterpret_cast<__nv_bfloat162*>(&g_a_lo[o + 2]) = __nv_bfloat162(lz, lw);
}

// ---------------- kernel 3: transpose + split weights: W[K,N] -> Bt[N,K] -----
__global__ __launch_bounds__(256) void wsplit(
    const float* __restrict__ W, __nv_bfloat16* __restrict__ Bth,
    __nv_bfloat16* __restrict__ Btl, int K, int N)
{
    __shared__ float t[32][33];
    int k0 = blockIdx.x * 32, n0 = blockIdx.y * 32;
    int tx = threadIdx.x % 32, ty = threadIdx.x / 32;
    #pragma unroll
    for (int i = 0; i < 32; i += 8)
        t[ty + i][tx] = W[(size_t)(k0 + ty + i) * N + n0 + tx];
    __syncthreads();
    #pragma unroll
    for (int i = 0; i < 32; i += 8) {
        float v = t[tx][ty + i];
        __nv_bfloat16 h, l; split_bf16(v, h, l);
        size_t o = (size_t)(n0 + ty + i) * K + k0 + tx;
        Bth[o] = h; Btl[o] = l;
    }
}

// ---------------- SELU --------------------------------------------------------
__device__ __forceinline__ float selu_f(float v) {
    const float scale = 1.0507009873554805f;
    const float alpha = 1.6732632423543772f;
    return v > 0.f ? scale * v : scale * alpha * (expf(v) - 1.f);
}

// ================= mma.sync bf16x3 GEMM =======================================
// C[M,N] = act(A @ Bt^T + bias). A=[M,K] bf16 hi/lo, Bt=[N,K] bf16 hi/lo.
// 3-term split: AhBh + AhBl + AlBh, fp32 accum (rel err ~2^-18).
// Block tile BM x BN, K-chunk 64, 8 warps, warp tile WM x WN.
template <int BM, int BN, int KTOT, int WM, int WN, bool ACT, bool SPLIT>
__global__ void __launch_bounds__(256) mma_gemm(
    const __nv_bfloat16* __restrict__ Ah, const __nv_bfloat16* __restrict__ Al,
    const __nv_bfloat16* __restrict__ Bh, const __nv_bfloat16* __restrict__ Bl,
    const float* __restrict__ bias,
    float* __restrict__ Cf, __nv_bfloat16* __restrict__ Ch,
    __nv_bfloat16* __restrict__ Cl, int Ntot)
{
    constexpr int KC  = 64;          // K elements per smem stage
    constexpr int RB  = 128;         // bytes per smem row (KC * 2)
    constexpr int WGM = BM / WM;     // warps along M
    constexpr int MT  = WM / 16;     // 16-row m tiles per warp
    constexpr int NT  = WN / 8;      // 8-col n tiles per warp
    static_assert((BM / WM) * (BN / WN) == 8, "8 warps");
    static_assert(NT % 2 == 0, "B ldmatrix.x4 covers 2 n-tiles");

    extern __shared__ char dsm[];
    uint32_t raw = smem_u32(dsm);
    uint32_t sb  = (raw + 1023u) & ~1023u;
    char* base   = dsm + (sb - raw);

    float* biass = (float*)base;                 // [BN] floats (<1024B: BN<=128? BN*4<=512 ok)
    const uint32_t AHI = sb + 1024;
    const uint32_t ALO = AHI + BM * RB;
    const uint32_t BHI = ALO + BM * RB;
    const uint32_t BLO = BHI + BN * RB;
    char* pAH = base + 1024;
    char* pAL = pAH + BM * RB;
    char* pBH = pAL + BM * RB;
    char* pBL = pBH + BN * RB;

    const int tid  = threadIdx.x;
    const int wid  = tid >> 5;
    const int lane = tid & 31;
    const int bm0  = blockIdx.y * BM;
    const int bn0  = blockIdx.x * BN;
    const int wm0  = (wid % WGM) * WM;
    const int wn0  = (wid / WGM) * WN;

    for (int i = tid; i < BN; i += 256) biass[i] = bias[bn0 + i];

    float acc[MT][NT][4];
    #pragma unroll
    for (int i = 0; i < MT; ++i)
        #pragma unroll
        for (int j = 0; j < NT; ++j)
            #pragma unroll
            for (int q = 0; q < 4; ++q) acc[i][j][q] = 0.f;

    // ldmatrix lane addressing pre-compute
    const int g  = lane >> 3;        // matrix index 0..3
    const int lr = lane & 7;         // row within 8x8 matrix
    // A: matrix g -> m += (g&1)*8, k byte += (g>>1)*16
    const uint32_t a_row_off = (uint32_t)(wm0 + (g & 1) * 8 + lr) * RB + (uint32_t)(g >> 1) * 16;
    // B: matrix g -> n += (g>>1)*8, k byte += (g&1)*16
    const uint32_t b_row_off = (uint32_t)(wn0 + (g >> 1) * 8 + lr) * RB + (uint32_t)(g & 1) * 16;

    constexpr int NCH = KTOT / KC;
    for (int kc = 0; kc < NCH; ++kc) {
        const int kel = kc * KC;
        // ---- global -> smem (SW128-swizzled 16B segments) ----
        constexpr int A_IT = BM * 8 / 256;
        #pragma unroll
        for (int i = 0; i < A_IT; ++i) {
            int e = tid + i * 256;
            int row = e >> 3, seg = e & 7;
            uint32_t so = SW128((uint32_t)(row * RB + seg * 16));
            size_t ga = (size_t)(bm0 + row) * KTOT + kel + seg * 8;
            *(uint4*)(pAH + so) = *(const uint4*)(Ah + ga);
            *(uint4*)(pAL + so) = *(const uint4*)(Al + ga);
        }
        constexpr int B_IT = BN * 8 / 256;
        #pragma unroll
        for (int i = 0; i < B_IT; ++i) {
            int e = tid + i * 256;
            int row = e >> 3, seg = e & 7;
            uint32_t so = SW128((uint32_t)(row * RB + seg * 16));
            size_t gb = (size_t)(bn0 + row) * KTOT + kel + seg * 8;
            *(uint4*)(pBH + so) = *(const uint4*)(Bh + gb);
            *(uint4*)(pBL + so) = *(const uint4*)(Bl + gb);
        }
        __syncthreads();

        // ---- 4 k16-steps over this chunk ----
        #pragma unroll
        for (int ks = 0; ks < 4; ++ks) {
            const uint32_t kb = (uint32_t)ks * 32;  // byte offset of k16 within row
            uint32_t a_hi[MT][4], a_lo[MT][4];
            #pragma unroll
            for (int mt = 0; mt < MT; ++mt) {
                uint32_t off = a_row_off + (uint32_t)mt * 16 * RB + kb;
                ldsm_x4(a_hi[mt], AHI + SW128(off));
                ldsm_x4(a_lo[mt], ALO + SW128(off));
            }
            uint32_t b_hi[NT][2], b_lo[NT][2];
            #pragma unroll
            for (int np = 0; np < NT / 2; ++np) {
                uint32_t off = b_row_off + (uint32_t)np * 16 * RB + kb;
                uint32_t th[4], tl[4];
                ldsm_x4(th, BHI + SW128(off));
                ldsm_x4(tl, BLO + SW128(off));
                b_hi[np * 2][0] = th[0]; b_hi[np * 2][1] = th[1];
                b_hi[np * 2 + 1][0] = th[2]; b_hi[np * 2 + 1][1] = th[3];
                b_lo[np * 2][0] = tl[0]; b_lo[np * 2][1] = tl[1];
                b_lo[np * 2 + 1][0] = tl[2]; b_lo[np * 2 + 1][1] = tl[3];
            }
            #pragma unroll
            for (int mt = 0; mt < MT; ++mt)
                #pragma unroll
                for (int nt = 0; nt < NT; ++nt) {
                    mma_bf16(acc[mt][nt], a_hi[mt], b_hi[nt]);
                    mma_bf16(acc[mt][nt], a_hi[mt], b_lo[nt]);
                    mma_bf16(acc[mt][nt], a_lo[mt], b_hi[nt]);
                }
        }
        __syncthreads();
    }

    // ---- epilogue: bias + act, write out ----
    const int er = lane >> 2;            // 0..7
    const int ec = (lane & 3) * 2;       // 0,2,4,6
    #pragma unroll
    for (int mt = 0; mt < MT; ++mt) {
        #pragma unroll
        for (int nt = 0; nt < NT; ++nt) {
            int col = wn0 + nt * 8 + ec;
            float bx = biass[col], by = biass[col + 1];
            float v0 = acc[mt][nt][0] + bx, v1 = acc[mt][nt][1] + by;
            float v2 = acc[mt][nt][2] + bx, v3 = acc[mt][nt][3] + by;
            if (ACT) { v0 = selu_f(v0); v1 = selu_f(v1); v2 = selu_f(v2); v3 = selu_f(v3); }
            size_t r0 = (size_t)(bm0 + wm0 + mt * 16 + er);
            size_t r1 = r0 + 8;
            size_t o0 = r0 * Ntot + bn0 + col;
            size_t o1 = r1 * Ntot + bn0 + col;
            if (SPLIT) {
                __nv_bfloat16 h0, l0, h1, l1, h2, l2, h3, l3;
                split_bf16(v0, h0, l0); split_bf16(v1, h1, l1);
                split_bf16(v2, h2, l2); split_bf16(v3, h3, l3);
                *reinterpret_cast<__nv_bfloat162*>(&Ch[o0]) = __nv_bfloat162(h0, h1);
                *reinterpret_cast<__nv_bfloat162*>(&Cl[o0]) = __nv_bfloat162(l0, l1);
                *reinterpret_cast<__nv_bfloat162*>(&Ch[o1]) = __nv_bfloat162(h2, h3);
                *reinterpret_cast<__nv_bfloat162*>(&Cl[o1]) = __nv_bfloat162(l2, l3);
            } else {
                *reinterpret_cast<float2*>(&Cf[o0]) = make_float2(v0, v1);
                *reinterpret_cast<float2*>(&Cf[o1]) = make_float2(v2, v3);
            }
        }
    }
}

// ---------------- launch ------------------------------------------------------
extern "C" void kernel_launch(void* const* d_in, const int* in_sizes, int n_in,
                              void* d_out, int out_size)
{
    const float* x     = (const float*)d_in[0];
    // d_in[1] = edge_index (unused), d_in[2] = edge_attr (unused)
    const float* u     = (const float*)d_in[3];
    const int*   batch = (const int*)d_in[4];
    const float* W1    = (const float*)d_in[5];
    const float* b1    = (const float*)d_in[6];
    const float* W2    = (const float*)d_in[7];
    const float* b2    = (const float*)d_in[8];
    float*       out   = (float*)d_out;

    const int n_nodes = in_sizes[0] / NODE_SIZE;

    void *p_ah, *p_al, *p_hh, *p_hl, *p_w1h, *p_w1l, *p_w2h, *p_w2l;
    cudaGetSymbolAddress(&p_ah,  g_a_hi);   cudaGetSymbolAddress(&p_al,  g_a_lo);
    cudaGetSymbolAddress(&p_hh,  g_h_hi);   cudaGetSymbolAddress(&p_hl,  g_h_lo);
    cudaGetSymbolAddress(&p_w1h, g_w1t_hi); cudaGetSymbolAddress(&p_w1l, g_w1t_lo);
    cudaGetSymbolAddress(&p_w2h, g_w2t_hi); cudaGetSymbolAddress(&p_w2l, g_w2t_lo);

    // smem: 1024 (align+bias) + 2*BM*128 + 2*BN*128
    constexpr int SM1 = 1024 + 2 * 128 * 128 + 2 * 128 * 128;  // 66560
    constexpr int SM2 = 1024 + 2 * 128 * 128 + 2 * 64 * 128;   // 50176
    cudaFuncSetAttribute((const void*)mma_gemm<128, 128, INPUT_SIZE, 64, 32, true, true>,
                         cudaFuncAttributeMaxDynamicSharedMemorySize, SM1);
    cudaFuncSetAttribute((const void*)mma_gemm<128, 64, HIDDEN_SIZE, 32, 32, false, false>,
                         cudaFuncAttributeMaxDynamicSharedMemorySize, SM2);

    zero_kernel<<<1024, 256>>>();

    int nblk = (n_nodes + ROWS_PER_BLOCK - 1) / ROWS_PER_BLOCK;
    seg_reduce<<<nblk, 128>>>(x, batch, n_nodes);

    wsplit<<<dim3(INPUT_SIZE / 32, HIDDEN_SIZE / 32), 256>>>(
        W1, (__nv_bfloat16*)p_w1h, (__nv_bfloat16*)p_w1l, INPUT_SIZE, HIDDEN_SIZE);
    wsplit<<<dim3(HIDDEN_SIZE / 32, GLOBAL_SIZE / 32), 256>>>(
        W2, (__nv_bfloat16*)p_w2h, (__nv_bfloat16*)p_w2l, HIDDEN_SIZE, GLOBAL_SIZE);

    prep_split<<<N_GRAPHS, 192>>>(u);

    // GEMM1: [4096,768] @ [768,1024] + b1, SELU -> g_h hi/lo (bf16 split out)
    mma_gemm<128, 128, INPUT_SIZE, 64, 32, true, true>
        <<<dim3(HIDDEN_SIZE / 128, N_GRAPHS / 128), 256, SM1>>>(
            (const __nv_bfloat16*)p_ah, (const __nv_bfloat16*)p_al,
            (const __nv_bfloat16*)p_w1h, (const __nv_bfloat16*)p_w1l,
            b1, nullptr, (__nv_bfloat16*)p_hh, (__nv_bfloat16*)p_hl, HIDDEN_SIZE);

    // GEMM2: [4096,1024] @ [1024,256] + b2 -> out (fp32)
    mma_gemm<128, 64, HIDDEN_SIZE, 32, 32, false, false>
        <<<dim3(GLOBAL_SIZE / 64, N_GRAPHS / 128), 256, SM2>>>(
            (const __nv_bfloat16*)p_hh, (const __nv_bfloat16*)p_hl,
            (const __nv_bfloat16*)p_w2h, (const __nv_bfloat16*)p_w2l,
            b2, out, nullptr, nullptr, GLOBAL_SIZE);
}

// round 5
// speedup vs baseline: 1.6129x; 1.0540x over previous
#include <cuda_runtime.h>
#include <cuda_bf16.h>
#include <math.h>
#include <stdint.h>

#define N_GRAPHS 4096
#define NODE_SIZE 512
#define GLOBAL_SIZE 256
#define HIDDEN_SIZE 1024
#define INPUT_SIZE 768   // GLOBAL_SIZE + NODE_SIZE

// ---------------- scratch (static device globals; no allocation) ------------
__device__ __nv_bfloat16 g_a_hi [N_GRAPHS * INPUT_SIZE];       // GEMM1 A split
__device__ __nv_bfloat16 g_a_lo [N_GRAPHS * INPUT_SIZE];
__device__ __nv_bfloat16 g_h_hi [N_GRAPHS * HIDDEN_SIZE];      // GEMM2 A split
__device__ __nv_bfloat16 g_h_lo [N_GRAPHS * HIDDEN_SIZE];
__device__ __nv_bfloat16 g_w1t_hi[HIDDEN_SIZE * INPUT_SIZE];   // W1^T split [N,K]
__device__ __nv_bfloat16 g_w1t_lo[HIDDEN_SIZE * INPUT_SIZE];
__device__ __nv_bfloat16 g_w2t_hi[GLOBAL_SIZE * HIDDEN_SIZE];  // W2^T split [N,K]
__device__ __nv_bfloat16 g_w2t_lo[GLOBAL_SIZE * HIDDEN_SIZE];

// ================= helpers ====================================================
__device__ __forceinline__ uint32_t smem_u32(const void* p) {
    uint32_t a;
    asm("{ .reg .u64 t; cvta.to.shared.u64 t, %1; cvt.u32.u64 %0, t; }"
        : "=r"(a) : "l"(p));
    return a;
}
#define SW128(o) ((o) ^ (((o) >> 3) & 0x70))

__device__ __forceinline__ void ldsm_x4(uint32_t* r, uint32_t addr) {
    asm volatile("ldmatrix.sync.aligned.m8n8.x4.shared.b16 {%0,%1,%2,%3}, [%4];"
                 : "=r"(r[0]), "=r"(r[1]), "=r"(r[2]), "=r"(r[3]) : "r"(addr));
}

__device__ __forceinline__ void mma_bf16(float* c, const uint32_t* a,
                                         const uint32_t* b) {
    asm volatile(
        "mma.sync.aligned.m16n8k16.row.col.f32.bf16.bf16.f32 "
        "{%0,%1,%2,%3}, {%4,%5,%6,%7}, {%8,%9}, {%0,%1,%2,%3};"
        : "+f"(c[0]), "+f"(c[1]), "+f"(c[2]), "+f"(c[3])
        : "r"(a[0]), "r"(a[1]), "r"(a[2]), "r"(a[3]), "r"(b[0]), "r"(b[1]));
}

__device__ __forceinline__ void cp16(uint32_t s, const void* g) {
    asm volatile("cp.async.cg.shared.global [%0], [%1], 16;" :: "r"(s), "l"(g));
}
__device__ __forceinline__ void cp_commit() {
    asm volatile("cp.async.commit_group;" ::: "memory");
}
template <int N>
__device__ __forceinline__ void cp_wait() {
    asm volatile("cp.async.wait_group %0;" :: "n"(N) : "memory");
}

// ---------------- bf16 split helpers ------------------------------------------
__device__ __forceinline__ void split_bf16(float v, __nv_bfloat16& h, __nv_bfloat16& l) {
    h = __float2bfloat16(v);
    l = __float2bfloat16(v - __bfloat162float(h));
}

// ---------------- kernel 1: fused segment-mean + concat + bf16 split ---------
// One CTA per graph. batch is sorted ascending -> binary search row range.
// No atomics, no zero pass, no intermediate g_sums.
__global__ __launch_bounds__(128) void mean_split(
    const float* __restrict__ x, const int* __restrict__ batch,
    const float* __restrict__ u, int n)
{
    const int g = blockIdx.x;

    // lower_bound(batch, g) and lower_bound(batch, g+1)
    int l = 0, r = n;
    while (l < r) { int m = (l + r) >> 1; if (__ldg(&batch[m]) < g) l = m + 1; else r = m; }
    const int lo = l;
    r = n;
    while (l < r) { int m = (l + r) >> 1; if (__ldg(&batch[m]) < g + 1) l = m + 1; else r = m; }
    const int hi = l;

    const int c = threadIdx.x * 4;           // 128 threads x 4 = 512 cols
    float4 acc = make_float4(0.f, 0.f, 0.f, 0.f);

    int rr = lo;
    for (; rr + 4 <= hi; rr += 4) {          // 4-row unroll -> MLP=4
        float4 v0 = *(const float4*)(x + (size_t)(rr + 0) * NODE_SIZE + c);
        float4 v1 = *(const float4*)(x + (size_t)(rr + 1) * NODE_SIZE + c);
        float4 v2 = *(const float4*)(x + (size_t)(rr + 2) * NODE_SIZE + c);
        float4 v3 = *(const float4*)(x + (size_t)(rr + 3) * NODE_SIZE + c);
        acc.x += (v0.x + v1.x) + (v2.x + v3.x);
        acc.y += (v0.y + v1.y) + (v2.y + v3.y);
        acc.z += (v0.z + v1.z) + (v2.z + v3.z);
        acc.w += (v0.w + v1.w) + (v2.w + v3.w);
    }
    for (; rr < hi; ++rr) {
        float4 v = *(const float4*)(x + (size_t)rr * NODE_SIZE + c);
        acc.x += v.x; acc.y += v.y; acc.z += v.z; acc.w += v.w;
    }

    const float inv = 1.f / fmaxf((float)(hi - lo), 1.f);
    const size_t rowo = (size_t)g * INPUT_SIZE;

    // mean -> cols [256, 768)
    {
        float4 v = make_float4(acc.x * inv, acc.y * inv, acc.z * inv, acc.w * inv);
        __nv_bfloat16 hx, hy, hz, hw, lx, ly, lz, lw;
        split_bf16(v.x, hx, lx); split_bf16(v.y, hy, ly);
        split_bf16(v.z, hz, lz); split_bf16(v.w, hw, lw);
        size_t o = rowo + GLOBAL_SIZE + c;
        *reinterpret_cast<__nv_bfloat162*>(&g_a_hi[o])     = __nv_bfloat162(hx, hy);
        *reinterpret_cast<__nv_bfloat162*>(&g_a_hi[o + 2]) = __nv_bfloat162(hz, hw);
        *reinterpret_cast<__nv_bfloat162*>(&g_a_lo[o])     = __nv_bfloat162(lx, ly);
        *reinterpret_cast<__nv_bfloat162*>(&g_a_lo[o + 2]) = __nv_bfloat162(lz, lw);
    }
    // u -> cols [0, 256)
    if (threadIdx.x < 64) {
        float4 v = *(const float4*)(u + (size_t)g * GLOBAL_SIZE + c);
        __nv_bfloat16 hx, hy, hz, hw, lx, ly, lz, lw;
        split_bf16(v.x, hx, lx); split_bf16(v.y, hy, ly);
        split_bf16(v.z, hz, lz); split_bf16(v.w, hw, lw);
        size_t o = rowo + c;
        *reinterpret_cast<__nv_bfloat162*>(&g_a_hi[o])     = __nv_bfloat162(hx, hy);
        *reinterpret_cast<__nv_bfloat162*>(&g_a_hi[o + 2]) = __nv_bfloat162(hz, hw);
        *reinterpret_cast<__nv_bfloat162*>(&g_a_lo[o])     = __nv_bfloat162(lx, ly);
        *reinterpret_cast<__nv_bfloat162*>(&g_a_lo[o + 2]) = __nv_bfloat162(lz, lw);
    }
}

// ---------------- kernel 2: transpose + split weights: W[K,N] -> Bt[N,K] -----
__global__ __launch_bounds__(256) void wsplit(
    const float* __restrict__ W, __nv_bfloat16* __restrict__ Bth,
    __nv_bfloat16* __restrict__ Btl, int K, int N)
{
    __shared__ float t[32][33];
    int k0 = blockIdx.x * 32, n0 = blockIdx.y * 32;
    int tx = threadIdx.x % 32, ty = threadIdx.x / 32;
    #pragma unroll
    for (int i = 0; i < 32; i += 8)
        t[ty + i][tx] = W[(size_t)(k0 + ty + i) * N + n0 + tx];
    __syncthreads();
    #pragma unroll
    for (int i = 0; i < 32; i += 8) {
        float v = t[tx][ty + i];
        __nv_bfloat16 h, l; split_bf16(v, h, l);
        size_t o = (size_t)(n0 + ty + i) * K + k0 + tx;
        Bth[o] = h; Btl[o] = l;
    }
}

// ---------------- SELU --------------------------------------------------------
__device__ __forceinline__ float selu_f(float v) {
    const float scale = 1.0507009873554805f;
    const float alpha = 1.6732632423543772f;
    return v > 0.f ? scale * v : scale * alpha * (expf(v) - 1.f);
}

// ================= mma.sync bf16x3 GEMM, cp.async double-buffered =============
// C[M,N] = act(A @ Bt^T + bias). A=[M,K] bf16 hi/lo, Bt=[N,K] bf16 hi/lo.
// 3-term split: AhBh + AhBl + AlBh, fp32 accum (rel err ~2^-18).
template <int BM, int BN, int KTOT, int WM, int WN, bool ACT, bool SPLIT>
__global__ void __launch_bounds__(256) mma_gemm(
    const __nv_bfloat16* __restrict__ Ah, const __nv_bfloat16* __restrict__ Al,
    const __nv_bfloat16* __restrict__ Bh, const __nv_bfloat16* __restrict__ Bl,
    const float* __restrict__ bias,
    float* __restrict__ Cf, __nv_bfloat16* __restrict__ Ch,
    __nv_bfloat16* __restrict__ Cl, int Ntot)
{
    constexpr int KC  = 64;          // K elements per smem stage
    constexpr int RB  = 128;         // bytes per smem row (KC * 2)
    constexpr int WGM = BM / WM;     // warps along M
    constexpr int MT  = WM / 16;
    constexpr int NT  = WN / 8;
    constexpr int STAGE = 2 * BM * RB + 2 * BN * RB;   // bytes per pipeline stage
    static_assert((BM / WM) * (BN / WN) == 8, "8 warps");
    static_assert(NT % 2 == 0, "B ldmatrix.x4 covers 2 n-tiles");

    extern __shared__ char dsm[];
    uint32_t raw = smem_u32(dsm);
    uint32_t sb  = (raw + 1023u) & ~1023u;
    char* base   = dsm + (sb - raw);

    float* biass = (float*)base;     // [BN] floats in first 1024B
    uint32_t AHIa[2], ALOa[2], BHIa[2], BLOa[2];
    #pragma unroll
    for (int s = 0; s < 2; ++s) {
        uint32_t b0 = sb + 1024 + s * STAGE;
        AHIa[s] = b0;
        ALOa[s] = b0 + BM * RB;
        BHIa[s] = b0 + 2 * BM * RB;
        BLOa[s] = b0 + 2 * BM * RB + BN * RB;
    }

    const int tid  = threadIdx.x;
    const int wid  = tid >> 5;
    const int lane = tid & 31;
    const int bm0  = blockIdx.y * BM;
    const int bn0  = blockIdx.x * BN;
    const int wm0  = (wid % WGM) * WM;
    const int wn0  = (wid / WGM) * WN;

    for (int i = tid; i < BN; i += 256) biass[i] = bias[bn0 + i];

    float acc[MT][NT][4];
    #pragma unroll
    for (int i = 0; i < MT; ++i)
        #pragma unroll
        for (int j = 0; j < NT; ++j)
            #pragma unroll
            for (int q = 0; q < 4; ++q) acc[i][j][q] = 0.f;

    // per-thread load coordinates (16B segments, SW128-swizzled)
    constexpr int A_IT = BM * 8 / 256;
    constexpr int B_IT = BN * 8 / 256;

    auto load_stage = [&](int kcc, int s) {
        const int kel = kcc * KC;
        #pragma unroll
        for (int i = 0; i < A_IT; ++i) {
            int e = tid + i * 256;
            int row = e >> 3, seg = e & 7;
            uint32_t so = SW128((uint32_t)(row * RB + seg * 16));
            size_t ga = (size_t)(bm0 + row) * KTOT + kel + seg * 8;
            cp16(AHIa[s] + so, Ah + ga);
            cp16(ALOa[s] + so, Al + ga);
        }
        #pragma unroll
        for (int i = 0; i < B_IT; ++i) {
            int e = tid + i * 256;
            int row = e >> 3, seg = e & 7;
            uint32_t so = SW128((uint32_t)(row * RB + seg * 16));
            size_t gb = (size_t)(bn0 + row) * KTOT + kel + seg * 8;
            cp16(BHIa[s] + so, Bh + gb);
            cp16(BLOa[s] + so, Bl + gb);
        }
        cp_commit();
    };

    // ldmatrix lane addressing
    const int g  = lane >> 3;
    const int lr = lane & 7;
    const uint32_t a_row_off = (uint32_t)(wm0 + (g & 1) * 8 + lr) * RB + (uint32_t)(g >> 1) * 16;
    const uint32_t b_row_off = (uint32_t)(wn0 + (g >> 1) * 8 + lr) * RB + (uint32_t)(g & 1) * 16;

    constexpr int NCH = KTOT / KC;
    load_stage(0, 0);

    for (int kc = 0; kc < NCH; ++kc) {
        const int buf = kc & 1;
        if (kc + 1 < NCH) {
            load_stage(kc + 1, buf ^ 1);
            cp_wait<1>();
        } else {
            cp_wait<0>();
        }
        __syncthreads();

        const uint32_t AHIb = AHIa[buf], ALOb = ALOa[buf];
        const uint32_t BHIb = BHIa[buf], BLOb = BLOa[buf];

        #pragma unroll
        for (int ks = 0; ks < 4; ++ks) {
            const uint32_t kb = (uint32_t)ks * 32;
            uint32_t a_hi[MT][4], a_lo[MT][4];
            #pragma unroll
            for (int mt = 0; mt < MT; ++mt) {
                uint32_t off = a_row_off + (uint32_t)mt * 16 * RB + kb;
                ldsm_x4(a_hi[mt], AHIb + SW128(off));
                ldsm_x4(a_lo[mt], ALOb + SW128(off));
            }
            uint32_t b_hi[NT][2], b_lo[NT][2];
            #pragma unroll
            for (int np = 0; np < NT / 2; ++np) {
                uint32_t off = b_row_off + (uint32_t)np * 16 * RB + kb;
                uint32_t th[4], tl[4];
                ldsm_x4(th, BHIb + SW128(off));
                ldsm_x4(tl, BLOb + SW128(off));
                b_hi[np * 2][0] = th[0]; b_hi[np * 2][1] = th[1];
                b_hi[np * 2 + 1][0] = th[2]; b_hi[np * 2 + 1][1] = th[3];
                b_lo[np * 2][0] = tl[0]; b_lo[np * 2][1] = tl[1];
                b_lo[np * 2 + 1][0] = tl[2]; b_lo[np * 2 + 1][1] = tl[3];
            }
            #pragma unroll
            for (int mt = 0; mt < MT; ++mt)
                #pragma unroll
                for (int nt = 0; nt < NT; ++nt) {
                    mma_bf16(acc[mt][nt], a_hi[mt], b_hi[nt]);
                    mma_bf16(acc[mt][nt], a_hi[mt], b_lo[nt]);
                    mma_bf16(acc[mt][nt], a_lo[mt], b_hi[nt]);
                }
        }
        __syncthreads();
    }

    // ---- epilogue: bias + act, write out ----
    const int er = lane >> 2;
    const int ec = (lane & 3) * 2;
    #pragma unroll
    for (int mt = 0; mt < MT; ++mt) {
        #pragma unroll
        for (int nt = 0; nt < NT; ++nt) {
            int col = wn0 + nt * 8 + ec;
            float bx = biass[col], by = biass[col + 1];
            float v0 = acc[mt][nt][0] + bx, v1 = acc[mt][nt][1] + by;
            float v2 = acc[mt][nt][2] + bx, v3 = acc[mt][nt][3] + by;
            if (ACT) { v0 = selu_f(v0); v1 = selu_f(v1); v2 = selu_f(v2); v3 = selu_f(v3); }
            size_t r0 = (size_t)(bm0 + wm0 + mt * 16 + er);
            size_t r1 = r0 + 8;
            size_t o0 = r0 * Ntot + bn0 + col;
            size_t o1 = r1 * Ntot + bn0 + col;
            if (SPLIT) {
                __nv_bfloat16 h0, l0, h1, l1, h2, l2, h3, l3;
                split_bf16(v0, h0, l0); split_bf16(v1, h1, l1);
                split_bf16(v2, h2, l2); split_bf16(v3, h3, l3);
                *reinterpret_cast<__nv_bfloat162*>(&Ch[o0]) = __nv_bfloat162(h0, h1);
                *reinterpret_cast<__nv_bfloat162*>(&Cl[o0]) = __nv_bfloat162(l0, l1);
                *reinterpret_cast<__nv_bfloat162*>(&Ch[o1]) = __nv_bfloat162(h2, h3);
                *reinterpret_cast<__nv_bfloat162*>(&Cl[o1]) = __nv_bfloat162(l2, l3);
            } else {
                *reinterpret_cast<float2*>(&Cf[o0]) = make_float2(v0, v1);
                *reinterpret_cast<float2*>(&Cf[o1]) = make_float2(v2, v3);
            }
        }
    }
}

// ---------------- launch ------------------------------------------------------
extern "C" void kernel_launch(void* const* d_in, const int* in_sizes, int n_in,
                              void* d_out, int out_size)
{
    const float* x     = (const float*)d_in[0];
    // d_in[1] = edge_index (unused), d_in[2] = edge_attr (unused)
    const float* u     = (const float*)d_in[3];
    const int*   batch = (const int*)d_in[4];
    const float* W1    = (const float*)d_in[5];
    const float* b1    = (const float*)d_in[6];
    const float* W2    = (const float*)d_in[7];
    const float* b2    = (const float*)d_in[8];
    float*       out   = (float*)d_out;

    const int n_nodes = in_sizes[0] / NODE_SIZE;

    void *p_ah, *p_al, *p_hh, *p_hl, *p_w1h, *p_w1l, *p_w2h, *p_w2l;
    cudaGetSymbolAddress(&p_ah,  g_a_hi);   cudaGetSymbolAddress(&p_al,  g_a_lo);
    cudaGetSymbolAddress(&p_hh,  g_h_hi);   cudaGetSymbolAddress(&p_hl,  g_h_lo);
    cudaGetSymbolAddress(&p_w1h, g_w1t_hi); cudaGetSymbolAddress(&p_w1l, g_w1t_lo);
    cudaGetSymbolAddress(&p_w2h, g_w2t_hi); cudaGetSymbolAddress(&p_w2l, g_w2t_lo);

    // smem: 1024 (align+bias) + 2 stages * (2*BM*128 + 2*BN*128)
    constexpr int SM1 = 1024 + 2 * (2 * 128 * 128 + 2 * 128 * 128);  // 132096
    constexpr int SM2 = 1024 + 2 * (2 * 128 * 128 + 2 * 64 * 128);   // 99328
    cudaFuncSetAttribute((const void*)mma_gemm<128, 128, INPUT_SIZE, 64, 32, true, true>,
                         cudaFuncAttributeMaxDynamicSharedMemorySize, SM1);
    cudaFuncSetAttribute((const void*)mma_gemm<128, 64, HIDDEN_SIZE, 32, 32, false, false>,
                         cudaFuncAttributeMaxDynamicSharedMemorySize, SM2);

    // weight transpose+split first (small, warms L2 for GEMMs)
    wsplit<<<dim3(INPUT_SIZE / 32, HIDDEN_SIZE / 32), 256>>>(
        W1, (__nv_bfloat16*)p_w1h, (__nv_bfloat16*)p_w1l, INPUT_SIZE, HIDDEN_SIZE);
    wsplit<<<dim3(HIDDEN_SIZE / 32, GLOBAL_SIZE / 32), 256>>>(
        W2, (__nv_bfloat16*)p_w2h, (__nv_bfloat16*)p_w2l, HIDDEN_SIZE, GLOBAL_SIZE);

    // fused segment-mean + concat + split (the HBM-bound pass over x)
    mean_split<<<N_GRAPHS, 128>>>(x, batch, u, n_nodes);

    // GEMM1: [4096,768] @ [768,1024] + b1, SELU -> g_h hi/lo (bf16 split out)
    mma_gemm<128, 128, INPUT_SIZE, 64, 32, true, true>
        <<<dim3(HIDDEN_SIZE / 128, N_GRAPHS / 128), 256, SM1>>>(
            (const __nv_bfloat16*)p_ah, (const __nv_bfloat16*)p_al,
            (const __nv_bfloat16*)p_w1h, (const __nv_bfloat16*)p_w1l,
            b1, nullptr, (__nv_bfloat16*)p_hh, (__nv_bfloat16*)p_hl, HIDDEN_SIZE);

    // GEMM2: [4096,1024] @ [1024,256] + b2 -> out (fp32)
    mma_gemm<128, 64, HIDDEN_SIZE, 32, 32, false, false>
        <<<dim3(GLOBAL_SIZE / 64, N_GRAPHS / 128), 256, SM2>>>(
            (const __nv_bfloat16*)p_hh, (const __nv_bfloat16*)p_hl,
            (const __nv_bfloat16*)p_w2h, (const __nv_bfloat16*)p_w2l,
            b2, out, nullptr, nullptr, GLOBAL_SIZE);
}

// round 6
// speedup vs baseline: 1.6499x; 1.0230x over previous
#include <cuda_runtime.h>
#include <cuda_bf16.h>
#include <math.h>
#include <stdint.h>

#define N_GRAPHS 4096
#define NODE_SIZE 512
#define GLOBAL_SIZE 256
#define HIDDEN_SIZE 1024
#define INPUT_SIZE 768   // GLOBAL_SIZE + NODE_SIZE

// ---------------- scratch (static device globals; no allocation) ------------
__device__ __nv_bfloat16 g_a_hi [N_GRAPHS * INPUT_SIZE];       // GEMM1 A split
__device__ __nv_bfloat16 g_a_lo [N_GRAPHS * INPUT_SIZE];
__device__ __nv_bfloat16 g_h_hi [N_GRAPHS * HIDDEN_SIZE];      // GEMM2 A split
__device__ __nv_bfloat16 g_h_lo [N_GRAPHS * HIDDEN_SIZE];
__device__ __nv_bfloat16 g_w1t_hi[HIDDEN_SIZE * INPUT_SIZE];   // W1^T split [N,K]
__device__ __nv_bfloat16 g_w1t_lo[HIDDEN_SIZE * INPUT_SIZE];
__device__ __nv_bfloat16 g_w2t_hi[GLOBAL_SIZE * HIDDEN_SIZE];  // W2^T split [N,K]
__device__ __nv_bfloat16 g_w2t_lo[GLOBAL_SIZE * HIDDEN_SIZE];

// ================= helpers ====================================================
__device__ __forceinline__ uint32_t smem_u32(const void* p) {
    uint32_t a;
    asm("{ .reg .u64 t; cvta.to.shared.u64 t, %1; cvt.u32.u64 %0, t; }"
        : "=r"(a) : "l"(p));
    return a;
}
#define SW128(o) ((o) ^ (((o) >> 3) & 0x70))

__device__ __forceinline__ void ldsm_x4(uint32_t* r, uint32_t addr) {
    asm volatile("ldmatrix.sync.aligned.m8n8.x4.shared.b16 {%0,%1,%2,%3}, [%4];"
                 : "=r"(r[0]), "=r"(r[1]), "=r"(r[2]), "=r"(r[3]) : "r"(addr));
}

__device__ __forceinline__ void mma_bf16(float* c, const uint32_t* a,
                                         const uint32_t* b) {
    asm volatile(
        "mma.sync.aligned.m16n8k16.row.col.f32.bf16.bf16.f32 "
        "{%0,%1,%2,%3}, {%4,%5,%6,%7}, {%8,%9}, {%0,%1,%2,%3};"
        : "+f"(c[0]), "+f"(c[1]), "+f"(c[2]), "+f"(c[3])
        : "r"(a[0]), "r"(a[1]), "r"(a[2]), "r"(a[3]), "r"(b[0]), "r"(b[1]));
}

__device__ __forceinline__ void cp16(uint32_t s, const void* g) {
    asm volatile("cp.async.cg.shared.global [%0], [%1], 16;" :: "r"(s), "l"(g));
}
__device__ __forceinline__ void cp_commit() {
    asm volatile("cp.async.commit_group;" ::: "memory");
}
template <int N>
__device__ __forceinline__ void cp_wait() {
    asm volatile("cp.async.wait_group %0;" :: "n"(N) : "memory");
}

// ---------------- bf16 split helpers ------------------------------------------
__device__ __forceinline__ void split_bf16(float v, __nv_bfloat16& h, __nv_bfloat16& l) {
    h = __float2bfloat16(v);
    l = __float2bfloat16(v - __bfloat162float(h));
}

// ---------------- kernel 1: fused segment-mean + concat + bf16 split ---------
// One CTA per graph. batch is sorted ascending -> binary search row range.
__global__ __launch_bounds__(128) void mean_split(
    const float* __restrict__ x, const int* __restrict__ batch,
    const float* __restrict__ u, int n)
{
    const int g = blockIdx.x;

    int l = 0, r = n;
    while (l < r) { int m = (l + r) >> 1; if (__ldg(&batch[m]) < g) l = m + 1; else r = m; }
    const int lo = l;
    r = n;
    while (l < r) { int m = (l + r) >> 1; if (__ldg(&batch[m]) < g + 1) l = m + 1; else r = m; }
    const int hi = l;

    const int c = threadIdx.x * 4;           // 128 threads x 4 = 512 cols
    float4 acc = make_float4(0.f, 0.f, 0.f, 0.f);

    int rr = lo;
    for (; rr + 8 <= hi; rr += 8) {          // 8-row unroll -> MLP=8
        float4 v0 = *(const float4*)(x + (size_t)(rr + 0) * NODE_SIZE + c);
        float4 v1 = *(const float4*)(x + (size_t)(rr + 1) * NODE_SIZE + c);
        float4 v2 = *(const float4*)(x + (size_t)(rr + 2) * NODE_SIZE + c);
        float4 v3 = *(const float4*)(x + (size_t)(rr + 3) * NODE_SIZE + c);
        float4 v4 = *(const float4*)(x + (size_t)(rr + 4) * NODE_SIZE + c);
        float4 v5 = *(const float4*)(x + (size_t)(rr + 5) * NODE_SIZE + c);
        float4 v6 = *(const float4*)(x + (size_t)(rr + 6) * NODE_SIZE + c);
        float4 v7 = *(const float4*)(x + (size_t)(rr + 7) * NODE_SIZE + c);
        acc.x += ((v0.x + v1.x) + (v2.x + v3.x)) + ((v4.x + v5.x) + (v6.x + v7.x));
        acc.y += ((v0.y + v1.y) + (v2.y + v3.y)) + ((v4.y + v5.y) + (v6.y + v7.y));
        acc.z += ((v0.z + v1.z) + (v2.z + v3.z)) + ((v4.z + v5.z) + (v6.z + v7.z));
        acc.w += ((v0.w + v1.w) + (v2.w + v3.w)) + ((v4.w + v5.w) + (v6.w + v7.w));
    }
    for (; rr < hi; ++rr) {
        float4 v = *(const float4*)(x + (size_t)rr * NODE_SIZE + c);
        acc.x += v.x; acc.y += v.y; acc.z += v.z; acc.w += v.w;
    }

    const float inv = 1.f / fmaxf((float)(hi - lo), 1.f);
    const size_t rowo = (size_t)g * INPUT_SIZE;

    {
        float4 v = make_float4(acc.x * inv, acc.y * inv, acc.z * inv, acc.w * inv);
        __nv_bfloat16 hx, hy, hz, hw, lx, ly, lz, lw;
        split_bf16(v.x, hx, lx); split_bf16(v.y, hy, ly);
        split_bf16(v.z, hz, lz); split_bf16(v.w, hw, lw);
        size_t o = rowo + GLOBAL_SIZE + c;
        *reinterpret_cast<__nv_bfloat162*>(&g_a_hi[o])     = __nv_bfloat162(hx, hy);
        *reinterpret_cast<__nv_bfloat162*>(&g_a_hi[o + 2]) = __nv_bfloat162(hz, hw);
        *reinterpret_cast<__nv_bfloat162*>(&g_a_lo[o])     = __nv_bfloat162(lx, ly);
        *reinterpret_cast<__nv_bfloat162*>(&g_a_lo[o + 2]) = __nv_bfloat162(lz, lw);
    }
    if (threadIdx.x < 64) {
        float4 v = *(const float4*)(u + (size_t)g * GLOBAL_SIZE + c);
        __nv_bfloat16 hx, hy, hz, hw, lx, ly, lz, lw;
        split_bf16(v.x, hx, lx); split_bf16(v.y, hy, ly);
        split_bf16(v.z, hz, lz); split_bf16(v.w, hw, lw);
        size_t o = rowo + c;
        *reinterpret_cast<__nv_bfloat162*>(&g_a_hi[o])     = __nv_bfloat162(hx, hy);
        *reinterpret_cast<__nv_bfloat162*>(&g_a_hi[o + 2]) = __nv_bfloat162(hz, hw);
        *reinterpret_cast<__nv_bfloat162*>(&g_a_lo[o])     = __nv_bfloat162(lx, ly);
        *reinterpret_cast<__nv_bfloat162*>(&g_a_lo[o + 2]) = __nv_bfloat162(lz, lw);
    }
}

// ---------------- kernel 2: transpose + split weights: W[K,N] -> Bt[N,K] -----
__global__ __launch_bounds__(256) void wsplit(
    const float* __restrict__ W, __nv_bfloat16* __restrict__ Bth,
    __nv_bfloat16* __restrict__ Btl, int K, int N)
{
    __shared__ float t[32][33];
    int k0 = blockIdx.x * 32, n0 = blockIdx.y * 32;
    int tx = threadIdx.x % 32, ty = threadIdx.x / 32;
    #pragma unroll
    for (int i = 0; i < 32; i += 8)
        t[ty + i][tx] = W[(size_t)(k0 + ty + i) * N + n0 + tx];
    __syncthreads();
    #pragma unroll
    for (int i = 0; i < 32; i += 8) {
        float v = t[tx][ty + i];
        __nv_bfloat16 h, l; split_bf16(v, h, l);
        size_t o = (size_t)(n0 + ty + i) * K + k0 + tx;
        Bth[o] = h; Btl[o] = l;
    }
}

// ---------------- SELU --------------------------------------------------------
__device__ __forceinline__ float selu_f(float v) {
    const float scale = 1.0507009873554805f;
    const float alpha = 1.6732632423543772f;
    return v > 0.f ? scale * v : scale * alpha * (expf(v) - 1.f);
}

// ================= mma.sync bf16x3 GEMM, cp.async double-buffered =============
// C[M,N] = act(A @ Bt^T + bias). A=[M,K] bf16 hi/lo, Bt=[N,K] bf16 hi/lo.
// 3-term split: AhBh + AhBl + AlBh, fp32 accum (rel err ~2^-18).
// 97KB smem -> 2 CTAs/SM (launch_bounds(256,2)) so barriers overlap across CTAs.
template <int BM, int BN, int KTOT, int WM, int WN, bool ACT, bool SPLIT>
__global__ void __launch_bounds__(256, 2) mma_gemm(
    const __nv_bfloat16* __restrict__ Ah, const __nv_bfloat16* __restrict__ Al,
    const __nv_bfloat16* __restrict__ Bh, const __nv_bfloat16* __restrict__ Bl,
    const float* __restrict__ bias,
    float* __restrict__ Cf, __nv_bfloat16* __restrict__ Ch,
    __nv_bfloat16* __restrict__ Cl, int Ntot)
{
    constexpr int KC  = 64;          // K elements per smem stage
    constexpr int RB  = 128;         // bytes per smem row (KC * 2)
    constexpr int WGM = BM / WM;     // warps along M
    constexpr int MT  = WM / 16;
    constexpr int NT  = WN / 8;
    constexpr int STAGE = 2 * BM * RB + 2 * BN * RB;
    static_assert((BM / WM) * (BN / WN) == 8, "8 warps");
    static_assert(NT % 2 == 0, "B ldmatrix.x4 covers 2 n-tiles");

    extern __shared__ char dsm[];
    uint32_t raw = smem_u32(dsm);
    uint32_t sb  = (raw + 1023u) & ~1023u;
    char* base   = dsm + (sb - raw);

    float* biass = (float*)base;     // [BN] floats in first 1024B
    uint32_t AHIa[2], ALOa[2], BHIa[2], BLOa[2];
    #pragma unroll
    for (int s = 0; s < 2; ++s) {
        uint32_t b0 = sb + 1024 + s * STAGE;
        AHIa[s] = b0;
        ALOa[s] = b0 + BM * RB;
        BHIa[s] = b0 + 2 * BM * RB;
        BLOa[s] = b0 + 2 * BM * RB + BN * RB;
    }

    const int tid  = threadIdx.x;
    const int wid  = tid >> 5;
    const int lane = tid & 31;
    const int bm0  = blockIdx.y * BM;
    const int bn0  = blockIdx.x * BN;
    const int wm0  = (wid % WGM) * WM;
    const int wn0  = (wid / WGM) * WN;

    for (int i = tid; i < BN; i += 256) biass[i] = bias[bn0 + i];

    float acc[MT][NT][4];
    #pragma unroll
    for (int i = 0; i < MT; ++i)
        #pragma unroll
        for (int j = 0; j < NT; ++j)
            #pragma unroll
            for (int q = 0; q < 4; ++q) acc[i][j][q] = 0.f;

    constexpr int A_IT = BM * 8 / 256;
    constexpr int B_IT = BN * 8 / 256;

    auto load_stage = [&](int kcc, int s) {
        const int kel = kcc * KC;
        #pragma unroll
        for (int i = 0; i < A_IT; ++i) {
            int e = tid + i * 256;
            int row = e >> 3, seg = e & 7;
            uint32_t so = SW128((uint32_t)(row * RB + seg * 16));
            size_t ga = (size_t)(bm0 + row) * KTOT + kel + seg * 8;
            cp16(AHIa[s] + so, Ah + ga);
            cp16(ALOa[s] + so, Al + ga);
        }
        #pragma unroll
        for (int i = 0; i < B_IT; ++i) {
            int e = tid + i * 256;
            int row = e >> 3, seg = e & 7;
            uint32_t so = SW128((uint32_t)(row * RB + seg * 16));
            size_t gb = (size_t)(bn0 + row) * KTOT + kel + seg * 8;
            cp16(BHIa[s] + so, Bh + gb);
            cp16(BLOa[s] + so, Bl + gb);
        }
        cp_commit();
    };

    const int g  = lane >> 3;
    const int lr = lane & 7;
    const uint32_t a_row_off = (uint32_t)(wm0 + (g & 1) * 8 + lr) * RB + (uint32_t)(g >> 1) * 16;
    const uint32_t b_row_off = (uint32_t)(wn0 + (g >> 1) * 8 + lr) * RB + (uint32_t)(g & 1) * 16;

    constexpr int NCH = KTOT / KC;
    load_stage(0, 0);

    for (int kc = 0; kc < NCH; ++kc) {
        const int buf = kc & 1;
        if (kc + 1 < NCH) {
            load_stage(kc + 1, buf ^ 1);
            cp_wait<1>();
        } else {
            cp_wait<0>();
        }
        __syncthreads();

        const uint32_t AHIb = AHIa[buf], ALOb = ALOa[buf];
        const uint32_t BHIb = BHIa[buf], BLOb = BLOa[buf];

        #pragma unroll
        for (int ks = 0; ks < 4; ++ks) {
            const uint32_t kb = (uint32_t)ks * 32;
            uint32_t a_hi[MT][4], a_lo[MT][4];
            #pragma unroll
            for (int mt = 0; mt < MT; ++mt) {
                uint32_t off = a_row_off + (uint32_t)mt * 16 * RB + kb;
                ldsm_x4(a_hi[mt], AHIb + SW128(off));
                ldsm_x4(a_lo[mt], ALOb + SW128(off));
            }
            uint32_t b_hi[NT][2], b_lo[NT][2];
            #pragma unroll
            for (int np = 0; np < NT / 2; ++np) {
                uint32_t off = b_row_off + (uint32_t)np * 16 * RB + kb;
                uint32_t th[4], tl[4];
                ldsm_x4(th, BHIb + SW128(off));
                ldsm_x4(tl, BLOb + SW128(off));
                b_hi[np * 2][0] = th[0]; b_hi[np * 2][1] = th[1];
                b_hi[np * 2 + 1][0] = th[2]; b_hi[np * 2 + 1][1] = th[3];
                b_lo[np * 2][0] = tl[0]; b_lo[np * 2][1] = tl[1];
                b_lo[np * 2 + 1][0] = tl[2]; b_lo[np * 2 + 1][1] = tl[3];
            }
            #pragma unroll
            for (int mt = 0; mt < MT; ++mt)
                #pragma unroll
                for (int nt = 0; nt < NT; ++nt) {
                    mma_bf16(acc[mt][nt], a_hi[mt], b_hi[nt]);
                    mma_bf16(acc[mt][nt], a_hi[mt], b_lo[nt]);
                    mma_bf16(acc[mt][nt], a_lo[mt], b_hi[nt]);
                }
        }
        __syncthreads();
    }

    // ---- epilogue: bias + act, write out ----
    const int er = lane >> 2;
    const int ec = (lane & 3) * 2;
    #pragma unroll
    for (int mt = 0; mt < MT; ++mt) {
        #pragma unroll
        for (int nt = 0; nt < NT; ++nt) {
            int col = wn0 + nt * 8 + ec;
            float bx = biass[col], by = biass[col + 1];
            float v0 = acc[mt][nt][0] + bx, v1 = acc[mt][nt][1] + by;
            float v2 = acc[mt][nt][2] + bx, v3 = acc[mt][nt][3] + by;
            if (ACT) { v0 = selu_f(v0); v1 = selu_f(v1); v2 = selu_f(v2); v3 = selu_f(v3); }
            size_t r0 = (size_t)(bm0 + wm0 + mt * 16 + er);
            size_t r1 = r0 + 8;
            size_t o0 = r0 * Ntot + bn0 + col;
            size_t o1 = r1 * Ntot + bn0 + col;
            if (SPLIT) {
                __nv_bfloat16 h0, l0, h1, l1, h2, l2, h3, l3;
                split_bf16(v0, h0, l0); split_bf16(v1, h1, l1);
                split_bf16(v2, h2, l2); split_bf16(v3, h3, l3);
                *reinterpret_cast<__nv_bfloat162*>(&Ch[o0]) = __nv_bfloat162(h0, h1);
                *reinterpret_cast<__nv_bfloat162*>(&Cl[o0]) = __nv_bfloat162(l0, l1);
                *reinterpret_cast<__nv_bfloat162*>(&Ch[o1]) = __nv_bfloat162(h2, h3);
                *reinterpret_cast<__nv_bfloat162*>(&Cl[o1]) = __nv_bfloat162(l2, l3);
            } else {
                *reinterpret_cast<float2*>(&Cf[o0]) = make_float2(v0, v1);
                *reinterpret_cast<float2*>(&Cf[o1]) = make_float2(v2, v3);
            }
        }
    }
}

// ---------------- launch ------------------------------------------------------
extern "C" void kernel_launch(void* const* d_in, const int* in_sizes, int n_in,
                              void* d_out, int out_size)
{
    const float* x     = (const float*)d_in[0];
    // d_in[1] = edge_index (unused), d_in[2] = edge_attr (unused)
    const float* u     = (const float*)d_in[3];
    const int*   batch = (const int*)d_in[4];
    const float* W1    = (const float*)d_in[5];
    const float* b1    = (const float*)d_in[6];
    const float* W2    = (const float*)d_in[7];
    const float* b2    = (const float*)d_in[8];
    float*       out   = (float*)d_out;

    const int n_nodes = in_sizes[0] / NODE_SIZE;

    void *p_ah, *p_al, *p_hh, *p_hl, *p_w1h, *p_w1l, *p_w2h, *p_w2l;
    cudaGetSymbolAddress(&p_ah,  g_a_hi);   cudaGetSymbolAddress(&p_al,  g_a_lo);
    cudaGetSymbolAddress(&p_hh,  g_h_hi);   cudaGetSymbolAddress(&p_hl,  g_h_lo);
    cudaGetSymbolAddress(&p_w1h, g_w1t_hi); cudaGetSymbolAddress(&p_w1l, g_w1t_lo);
    cudaGetSymbolAddress(&p_w2h, g_w2t_hi); cudaGetSymbolAddress(&p_w2l, g_w2t_lo);

    // smem: 1024 (align+bias) + 2 stages * (2*BM*128 + 2*BN*128) = 99328 B
    constexpr int SMB = 1024 + 2 * (2 * 128 * 128 + 2 * 64 * 128);
    cudaFuncSetAttribute((const void*)mma_gemm<128, 64, INPUT_SIZE, 32, 32, true, true>,
                         cudaFuncAttributeMaxDynamicSharedMemorySize, SMB);
    cudaFuncSetAttribute((const void*)mma_gemm<128, 64, HIDDEN_SIZE, 32, 32, false, false>,
                         cudaFuncAttributeMaxDynamicSharedMemorySize, SMB);

    // weight transpose+split first (small, warms L2 for GEMMs)
    wsplit<<<dim3(INPUT_SIZE / 32, HIDDEN_SIZE / 32), 256>>>(
        W1, (__nv_bfloat16*)p_w1h, (__nv_bfloat16*)p_w1l, INPUT_SIZE, HIDDEN_SIZE);
    wsplit<<<dim3(HIDDEN_SIZE / 32, GLOBAL_SIZE / 32), 256>>>(
        W2, (__nv_bfloat16*)p_w2h, (__nv_bfloat16*)p_w2l, HIDDEN_SIZE, GLOBAL_SIZE);

    // fused segment-mean + concat + split (the HBM-bound pass over x)
    mean_split<<<N_GRAPHS, 128>>>(x, batch, u, n_nodes);

    // GEMM1: [4096,768] @ [768,1024] + b1, SELU -> g_h hi/lo (bf16 split out)
    mma_gemm<128, 64, INPUT_SIZE, 32, 32, true, true>
        <<<dim3(HIDDEN_SIZE / 64, N_GRAPHS / 128), 256, SMB>>>(
            (const __nv_bfloat16*)p_ah, (const __nv_bfloat16*)p_al,
            (const __nv_bfloat16*)p_w1h, (const __nv_bfloat16*)p_w1l,
            b1, nullptr, (__nv_bfloat16*)p_hh, (__nv_bfloat16*)p_hl, HIDDEN_SIZE);

    // GEMM2: [4096,1024] @ [1024,256] + b2 -> out (fp32)
    mma_gemm<128, 64, HIDDEN_SIZE, 32, 32, false, false>
        <<<dim3(GLOBAL_SIZE / 64, N_GRAPHS / 128), 256, SMB>>>(
            (const __nv_bfloat16*)p_hh, (const __nv_bfloat16*)p_hl,
            (const __nv_bfloat16*)p_w2h, (const __nv_bfloat16*)p_w2l,
            b2, out, nullptr, nullptr, GLOBAL_SIZE);
}

// round 7
// speedup vs baseline: 1.6505x; 1.0004x over previous
#include <cuda_runtime.h>
#include <cuda_bf16.h>
#include <math.h>
#include <stdint.h>

#define N_GRAPHS 4096
#define NODE_SIZE 512
#define GLOBAL_SIZE 256
#define HIDDEN_SIZE 1024
#define INPUT_SIZE 768   // GLOBAL_SIZE + NODE_SIZE

// ---------------- scratch (static device globals; no allocation) ------------
__device__ __nv_bfloat16 g_a_hi [N_GRAPHS * INPUT_SIZE];       // GEMM1 A split
__device__ __nv_bfloat16 g_a_lo [N_GRAPHS * INPUT_SIZE];
__device__ __nv_bfloat16 g_h_hi [N_GRAPHS * HIDDEN_SIZE];      // GEMM2 A split
__device__ __nv_bfloat16 g_h_lo [N_GRAPHS * HIDDEN_SIZE];
__device__ __nv_bfloat16 g_w1t_hi[HIDDEN_SIZE * INPUT_SIZE];   // W1^T split [N,K]
__device__ __nv_bfloat16 g_w1t_lo[HIDDEN_SIZE * INPUT_SIZE];
__device__ __nv_bfloat16 g_w2t_hi[GLOBAL_SIZE * HIDDEN_SIZE];  // W2^T split [N,K]
__device__ __nv_bfloat16 g_w2t_lo[GLOBAL_SIZE * HIDDEN_SIZE];

// ================= helpers ====================================================
__device__ __forceinline__ uint32_t smem_u32(const void* p) {
    uint32_t a;
    asm("{ .reg .u64 t; cvta.to.shared.u64 t, %1; cvt.u32.u64 %0, t; }"
        : "=r"(a) : "l"(p));
    return a;
}
#define SW128(o) ((o) ^ (((o) >> 3) & 0x70))

__device__ __forceinline__ void ldsm_x4(uint32_t* r, uint32_t addr) {
    asm volatile("ldmatrix.sync.aligned.m8n8.x4.shared.b16 {%0,%1,%2,%3}, [%4];"
                 : "=r"(r[0]), "=r"(r[1]), "=r"(r[2]), "=r"(r[3]) : "r"(addr));
}

__device__ __forceinline__ void mma_bf16(float* c, const uint32_t* a,
                                         const uint32_t* b) {
    asm volatile(
        "mma.sync.aligned.m16n8k16.row.col.f32.bf16.bf16.f32 "
        "{%0,%1,%2,%3}, {%4,%5,%6,%7}, {%8,%9}, {%0,%1,%2,%3};"
        : "+f"(c[0]), "+f"(c[1]), "+f"(c[2]), "+f"(c[3])
        : "r"(a[0]), "r"(a[1]), "r"(a[2]), "r"(a[3]), "r"(b[0]), "r"(b[1]));
}

__device__ __forceinline__ void cp16(uint32_t s, const void* g) {
    asm volatile("cp.async.cg.shared.global [%0], [%1], 16;" :: "r"(s), "l"(g));
}
__device__ __forceinline__ void cp_commit() {
    asm volatile("cp.async.commit_group;" ::: "memory");
}
template <int N>
__device__ __forceinline__ void cp_wait() {
    asm volatile("cp.async.wait_group %0;" :: "n"(N) : "memory");
}

// ---------------- bf16 split helpers ------------------------------------------
__device__ __forceinline__ void split_bf16(float v, __nv_bfloat16& h, __nv_bfloat16& l) {
    h = __float2bfloat16(v);
    l = __float2bfloat16(v - __bfloat162float(h));
}

// ---------------- kernel 1: fused segment-mean + concat + bf16 split ---------
// One CTA per graph. batch is sorted ascending -> binary search row range.
__global__ __launch_bounds__(128) void mean_split(
    const float* __restrict__ x, const int* __restrict__ batch,
    const float* __restrict__ u, int n)
{
    const int g = blockIdx.x;

    int l = 0, r = n;
    while (l < r) { int m = (l + r) >> 1; if (__ldg(&batch[m]) < g) l = m + 1; else r = m; }
    const int lo = l;
    r = n;
    while (l < r) { int m = (l + r) >> 1; if (__ldg(&batch[m]) < g + 1) l = m + 1; else r = m; }
    const int hi = l;

    const int c = threadIdx.x * 4;           // 128 threads x 4 = 512 cols
    float4 acc = make_float4(0.f, 0.f, 0.f, 0.f);

    int rr = lo;
    for (; rr + 8 <= hi; rr += 8) {          // 8-row unroll -> MLP=8
        float4 v0 = *(const float4*)(x + (size_t)(rr + 0) * NODE_SIZE + c);
        float4 v1 = *(const float4*)(x + (size_t)(rr + 1) * NODE_SIZE + c);
        float4 v2 = *(const float4*)(x + (size_t)(rr + 2) * NODE_SIZE + c);
        float4 v3 = *(const float4*)(x + (size_t)(rr + 3) * NODE_SIZE + c);
        float4 v4 = *(const float4*)(x + (size_t)(rr + 4) * NODE_SIZE + c);
        float4 v5 = *(const float4*)(x + (size_t)(rr + 5) * NODE_SIZE + c);
        float4 v6 = *(const float4*)(x + (size_t)(rr + 6) * NODE_SIZE + c);
        float4 v7 = *(const float4*)(x + (size_t)(rr + 7) * NODE_SIZE + c);
        acc.x += ((v0.x + v1.x) + (v2.x + v3.x)) + ((v4.x + v5.x) + (v6.x + v7.x));
        acc.y += ((v0.y + v1.y) + (v2.y + v3.y)) + ((v4.y + v5.y) + (v6.y + v7.y));
        acc.z += ((v0.z + v1.z) + (v2.z + v3.z)) + ((v4.z + v5.z) + (v6.z + v7.z));
        acc.w += ((v0.w + v1.w) + (v2.w + v3.w)) + ((v4.w + v5.w) + (v6.w + v7.w));
    }
    for (; rr < hi; ++rr) {
        float4 v = *(const float4*)(x + (size_t)rr * NODE_SIZE + c);
        acc.x += v.x; acc.y += v.y; acc.z += v.z; acc.w += v.w;
    }

    const float inv = 1.f / fmaxf((float)(hi - lo), 1.f);
    const size_t rowo = (size_t)g * INPUT_SIZE;

    {
        float4 v = make_float4(acc.x * inv, acc.y * inv, acc.z * inv, acc.w * inv);
        __nv_bfloat16 hx, hy, hz, hw, lx, ly, lz, lw;
        split_bf16(v.x, hx, lx); split_bf16(v.y, hy, ly);
        split_bf16(v.z, hz, lz); split_bf16(v.w, hw, lw);
        size_t o = rowo + GLOBAL_SIZE + c;
        *reinterpret_cast<__nv_bfloat162*>(&g_a_hi[o])     = __nv_bfloat162(hx, hy);
        *reinterpret_cast<__nv_bfloat162*>(&g_a_hi[o + 2]) = __nv_bfloat162(hz, hw);
        *reinterpret_cast<__nv_bfloat162*>(&g_a_lo[o])     = __nv_bfloat162(lx, ly);
        *reinterpret_cast<__nv_bfloat162*>(&g_a_lo[o + 2]) = __nv_bfloat162(lz, lw);
    }
    if (threadIdx.x < 64) {
        float4 v = *(const float4*)(u + (size_t)g * GLOBAL_SIZE + c);
        __nv_bfloat16 hx, hy, hz, hw, lx, ly, lz, lw;
        split_bf16(v.x, hx, lx); split_bf16(v.y, hy, ly);
        split_bf16(v.z, hz, lz); split_bf16(v.w, hw, lw);
        size_t o = rowo + c;
        *reinterpret_cast<__nv_bfloat162*>(&g_a_hi[o])     = __nv_bfloat162(hx, hy);
        *reinterpret_cast<__nv_bfloat162*>(&g_a_hi[o + 2]) = __nv_bfloat162(hz, hw);
        *reinterpret_cast<__nv_bfloat162*>(&g_a_lo[o])     = __nv_bfloat162(lx, ly);
        *reinterpret_cast<__nv_bfloat162*>(&g_a_lo[o + 2]) = __nv_bfloat162(lz, lw);
    }
}

// ---------------- kernel 2: transpose + split weights: W[K,N] -> Bt[N,K] -----
__global__ __launch_bounds__(256) void wsplit(
    const float* __restrict__ W, __nv_bfloat16* __restrict__ Bth,
    __nv_bfloat16* __restrict__ Btl, int K, int N)
{
    __shared__ float t[32][33];
    int k0 = blockIdx.x * 32, n0 = blockIdx.y * 32;
    int tx = threadIdx.x % 32, ty = threadIdx.x / 32;
    #pragma unroll
    for (int i = 0; i < 32; i += 8)
        t[ty + i][tx] = W[(size_t)(k0 + ty + i) * N + n0 + tx];
    __syncthreads();
    #pragma unroll
    for (int i = 0; i < 32; i += 8) {
        float v = t[tx][ty + i];
        __nv_bfloat16 h, l; split_bf16(v, h, l);
        size_t o = (size_t)(n0 + ty + i) * K + k0 + tx;
        Bth[o] = h; Btl[o] = l;
    }
}

// ---------------- SELU --------------------------------------------------------
__device__ __forceinline__ float selu_f(float v) {
    const float scale = 1.0507009873554805f;
    const float alpha = 1.6732632423543772f;
    return v > 0.f ? scale * v : scale * alpha * (expf(v) - 1.f);
}

// ================= mma.sync bf16x3 GEMM, cp.async double-buffered =============
// C[M,N] = act(A @ Bt^T + bias). A=[M,K] bf16 hi/lo, Bt=[N,K] bf16 hi/lo.
// 3-term split: AhBh + AhBl + AlBh, fp32 accum (rel err ~2^-18).
// Inner loop interleaves hi-ldsm -> hh-MMA -> lo-ldsm -> hl/lh-MMA so tensor
// work hides the second ldmatrix wave.
template <int BM, int BN, int KTOT, int WM, int WN, int MINCTA, bool ACT, bool SPLIT>
__global__ void __launch_bounds__(256, MINCTA) mma_gemm(
    const __nv_bfloat16* __restrict__ Ah, const __nv_bfloat16* __restrict__ Al,
    const __nv_bfloat16* __restrict__ Bh, const __nv_bfloat16* __restrict__ Bl,
    const float* __restrict__ bias,
    float* __restrict__ Cf, __nv_bfloat16* __restrict__ Ch,
    __nv_bfloat16* __restrict__ Cl, int Ntot)
{
    constexpr int KC  = 64;          // K elements per smem stage
    constexpr int RB  = 128;         // bytes per smem row (KC * 2)
    constexpr int WGM = BM / WM;     // warps along M
    constexpr int MT  = WM / 16;
    constexpr int NT  = WN / 8;
    constexpr int STAGE = 2 * BM * RB + 2 * BN * RB;
    static_assert((BM / WM) * (BN / WN) == 8, "8 warps");
    static_assert(NT % 2 == 0, "B ldmatrix.x4 covers 2 n-tiles");

    extern __shared__ char dsm[];
    uint32_t raw = smem_u32(dsm);
    uint32_t sb  = (raw + 1023u) & ~1023u;
    char* base   = dsm + (sb - raw);

    float* biass = (float*)base;     // [BN] floats in first 1024B
    uint32_t AHIa[2], ALOa[2], BHIa[2], BLOa[2];
    #pragma unroll
    for (int s = 0; s < 2; ++s) {
        uint32_t b0 = sb + 1024 + s * STAGE;
        AHIa[s] = b0;
        ALOa[s] = b0 + BM * RB;
        BHIa[s] = b0 + 2 * BM * RB;
        BLOa[s] = b0 + 2 * BM * RB + BN * RB;
    }

    const int tid  = threadIdx.x;
    const int wid  = tid >> 5;
    const int lane = tid & 31;
    const int bm0  = blockIdx.y * BM;
    const int bn0  = blockIdx.x * BN;
    const int wm0  = (wid % WGM) * WM;
    const int wn0  = (wid / WGM) * WN;

    for (int i = tid; i < BN; i += 256) biass[i] = bias[bn0 + i];

    float acc[MT][NT][4];
    #pragma unroll
    for (int i = 0; i < MT; ++i)
        #pragma unroll
        for (int j = 0; j < NT; ++j)
            #pragma unroll
            for (int q = 0; q < 4; ++q) acc[i][j][q] = 0.f;

    constexpr int A_IT = BM * 8 / 256;
    constexpr int B_IT = BN * 8 / 256;

    auto load_stage = [&](int kcc, int s) {
        const int kel = kcc * KC;
        #pragma unroll
        for (int i = 0; i < A_IT; ++i) {
            int e = tid + i * 256;
            int row = e >> 3, seg = e & 7;
            uint32_t so = SW128((uint32_t)(row * RB + seg * 16));
            size_t ga = (size_t)(bm0 + row) * KTOT + kel + seg * 8;
            cp16(AHIa[s] + so, Ah + ga);
            cp16(ALOa[s] + so, Al + ga);
        }
        #pragma unroll
        for (int i = 0; i < B_IT; ++i) {
            int e = tid + i * 256;
            int row = e >> 3, seg = e & 7;
            uint32_t so = SW128((uint32_t)(row * RB + seg * 16));
            size_t gb = (size_t)(bn0 + row) * KTOT + kel + seg * 8;
            cp16(BHIa[s] + so, Bh + gb);
            cp16(BLOa[s] + so, Bl + gb);
        }
        cp_commit();
    };

    const int g  = lane >> 3;
    const int lr = lane & 7;
    const uint32_t a_row_off = (uint32_t)(wm0 + (g & 1) * 8 + lr) * RB + (uint32_t)(g >> 1) * 16;
    const uint32_t b_row_off = (uint32_t)(wn0 + (g >> 1) * 8 + lr) * RB + (uint32_t)(g & 1) * 16;

    constexpr int NCH = KTOT / KC;
    load_stage(0, 0);

    for (int kc = 0; kc < NCH; ++kc) {
        const int buf = kc & 1;
        if (kc + 1 < NCH) {
            load_stage(kc + 1, buf ^ 1);
            cp_wait<1>();
        } else {
            cp_wait<0>();
        }
        __syncthreads();

        const uint32_t AHIb = AHIa[buf], ALOb = ALOa[buf];
        const uint32_t BHIb = BHIa[buf], BLOb = BLOa[buf];

        #pragma unroll
        for (int ks = 0; ks < 4; ++ks) {
            const uint32_t kb = (uint32_t)ks * 32;

            // ---- wave 1: hi fragments ----
            uint32_t a_hi[MT][4];
            #pragma unroll
            for (int mt = 0; mt < MT; ++mt)
                ldsm_x4(a_hi[mt], AHIb + SW128(a_row_off + (uint32_t)mt * 16 * RB + kb));
            uint32_t b_hi[NT][2];
            #pragma unroll
            for (int np = 0; np < NT / 2; ++np) {
                uint32_t th[4];
                ldsm_x4(th, BHIb + SW128(b_row_off + (uint32_t)np * 16 * RB + kb));
                b_hi[np * 2][0] = th[0]; b_hi[np * 2][1] = th[1];
                b_hi[np * 2 + 1][0] = th[2]; b_hi[np * 2 + 1][1] = th[3];
            }

            // ---- hh MMAs (overlap with the lo ldsm wave below) ----
            #pragma unroll
            for (int mt = 0; mt < MT; ++mt)
                #pragma unroll
                for (int nt = 0; nt < NT; ++nt)
                    mma_bf16(acc[mt][nt], a_hi[mt], b_hi[nt]);

            // ---- wave 2: lo fragments ----
            uint32_t a_lo[MT][4];
            #pragma unroll
            for (int mt = 0; mt < MT; ++mt)
                ldsm_x4(a_lo[mt], ALOb + SW128(a_row_off + (uint32_t)mt * 16 * RB + kb));
            uint32_t b_lo[NT][2];
            #pragma unroll
            for (int np = 0; np < NT / 2; ++np) {
                uint32_t tl[4];
                ldsm_x4(tl, BLOb + SW128(b_row_off + (uint32_t)np * 16 * RB + kb));
                b_lo[np * 2][0] = tl[0]; b_lo[np * 2][1] = tl[1];
                b_lo[np * 2 + 1][0] = tl[2]; b_lo[np * 2 + 1][1] = tl[3];
            }

            // ---- cross terms ----
            #pragma unroll
            for (int mt = 0; mt < MT; ++mt)
                #pragma unroll
                for (int nt = 0; nt < NT; ++nt) {
                    mma_bf16(acc[mt][nt], a_hi[mt], b_lo[nt]);
                    mma_bf16(acc[mt][nt], a_lo[mt], b_hi[nt]);
                }
        }
        __syncthreads();
    }

    // ---- epilogue: bias + act, write out ----
    const int er = lane >> 2;
    const int ec = (lane & 3) * 2;
    #pragma unroll
    for (int mt = 0; mt < MT; ++mt) {
        #pragma unroll
        for (int nt = 0; nt < NT; ++nt) {
            int col = wn0 + nt * 8 + ec;
            float bx = biass[col], by = biass[col + 1];
            float v0 = acc[mt][nt][0] + bx, v1 = acc[mt][nt][1] + by;
            float v2 = acc[mt][nt][2] + bx, v3 = acc[mt][nt][3] + by;
            if (ACT) { v0 = selu_f(v0); v1 = selu_f(v1); v2 = selu_f(v2); v3 = selu_f(v3); }
            size_t r0 = (size_t)(bm0 + wm0 + mt * 16 + er);
            size_t r1 = r0 + 8;
            size_t o0 = r0 * Ntot + bn0 + col;
            size_t o1 = r1 * Ntot + bn0 + col;
            if (SPLIT) {
                __nv_bfloat16 h0, l0, h1, l1, h2, l2, h3, l3;
                split_bf16(v0, h0, l0); split_bf16(v1, h1, l1);
                split_bf16(v2, h2, l2); split_bf16(v3, h3, l3);
                *reinterpret_cast<__nv_bfloat162*>(&Ch[o0]) = __nv_bfloat162(h0, h1);
                *reinterpret_cast<__nv_bfloat162*>(&Cl[o0]) = __nv_bfloat162(l0, l1);
                *reinterpret_cast<__nv_bfloat162*>(&Ch[o1]) = __nv_bfloat162(h2, h3);
                *reinterpret_cast<__nv_bfloat162*>(&Cl[o1]) = __nv_bfloat162(l2, l3);
            } else {
                *reinterpret_cast<float2*>(&Cf[o0]) = make_float2(v0, v1);
                *reinterpret_cast<float2*>(&Cf[o1]) = make_float2(v2, v3);
            }
        }
    }
}

// ---------------- launch ------------------------------------------------------
extern "C" void kernel_launch(void* const* d_in, const int* in_sizes, int n_in,
                              void* d_out, int out_size)
{
    const float* x     = (const float*)d_in[0];
    // d_in[1] = edge_index (unused), d_in[2] = edge_attr (unused)
    const float* u     = (const float*)d_in[3];
    const int*   batch = (const int*)d_in[4];
    const float* W1    = (const float*)d_in[5];
    const float* b1    = (const float*)d_in[6];
    const float* W2    = (const float*)d_in[7];
    const float* b2    = (const float*)d_in[8];
    float*       out   = (float*)d_out;

    const int n_nodes = in_sizes[0] / NODE_SIZE;

    void *p_ah, *p_al, *p_hh, *p_hl, *p_w1h, *p_w1l, *p_w2h, *p_w2l;
    cudaGetSymbolAddress(&p_ah,  g_a_hi);   cudaGetSymbolAddress(&p_al,  g_a_lo);
    cudaGetSymbolAddress(&p_hh,  g_h_hi);   cudaGetSymbolAddress(&p_hl,  g_h_lo);
    cudaGetSymbolAddress(&p_w1h, g_w1t_hi); cudaGetSymbolAddress(&p_w1l, g_w1t_lo);
    cudaGetSymbolAddress(&p_w2h, g_w2t_hi); cudaGetSymbolAddress(&p_w2l, g_w2t_lo);

    // GEMM1: BM=128,BN=64 -> smem = 1024 + 2*(2*128*128 + 2*64*128) = 99328 B
    constexpr int SMB1 = 1024 + 2 * (2 * 128 * 128 + 2 * 64 * 128);
    // GEMM2: BM=64,BN=64  -> smem = 1024 + 2*(2*64*128 + 2*64*128)  = 66560 B
    constexpr int SMB2 = 1024 + 2 * (2 * 64 * 128 + 2 * 64 * 128);
    cudaFuncSetAttribute(
        (const void*)mma_gemm<128, 64, INPUT_SIZE, 32, 32, 2, true, true>,
        cudaFuncAttributeMaxDynamicSharedMemorySize, SMB1);
    cudaFuncSetAttribute(
        (const void*)mma_gemm<64, 64, HIDDEN_SIZE, 16, 32, 3, false, false>,
        cudaFuncAttributeMaxDynamicSharedMemorySize, SMB2);

    // weight transpose+split (small)
    wsplit<<<dim3(INPUT_SIZE / 32, HIDDEN_SIZE / 32), 256>>>(
        W1, (__nv_bfloat16*)p_w1h, (__nv_bfloat16*)p_w1l, INPUT_SIZE, HIDDEN_SIZE);
    wsplit<<<dim3(HIDDEN_SIZE / 32, GLOBAL_SIZE / 32), 256>>>(
        W2, (__nv_bfloat16*)p_w2h, (__nv_bfloat16*)p_w2l, HIDDEN_SIZE, GLOBAL_SIZE);

    // fused segment-mean + concat + split (the HBM-bound pass over x)
    mean_split<<<N_GRAPHS, 128>>>(x, batch, u, n_nodes);

    // GEMM1: [4096,768] @ [768,1024] + b1, SELU -> g_h hi/lo (bf16 split out)
    mma_gemm<128, 64, INPUT_SIZE, 32, 32, 2, true, true>
        <<<dim3(HIDDEN_SIZE / 64, N_GRAPHS / 128), 256, SMB1>>>(
            (const __nv_bfloat16*)p_ah, (const __nv_bfloat16*)p_al,
            (const __nv_bfloat16*)p_w1h, (const __nv_bfloat16*)p_w1l,
            b1, nullptr, (__nv_bfloat16*)p_hh, (__nv_bfloat16*)p_hl, HIDDEN_SIZE);

    // GEMM2: [4096,1024] @ [1024,256] + b2 -> out (fp32), 256 CTAs for full chip
    mma_gemm<64, 64, HIDDEN_SIZE, 16, 32, 3, false, false>
        <<<dim3(GLOBAL_SIZE / 64, N_GRAPHS / 64), 256, SMB2>>>(
            (const __nv_bfloat16*)p_hh, (const __nv_bfloat16*)p_hl,
            (const __nv_bfloat16*)p_w2h, (const __nv_bfloat16*)p_w2l,
            b2, out, nullptr, nullptr, GLOBAL_SIZE);
}

// round 8
// speedup vs baseline: 1.7597x; 1.0661x over previous
#include <cuda_runtime.h>
#include <cuda_bf16.h>
#include <math.h>
#include <stdint.h>

#define N_GRAPHS 4096
#define NODE_SIZE 512
#define GLOBAL_SIZE 256
#define HIDDEN_SIZE 1024
#define INPUT_SIZE 768   // GLOBAL_SIZE + NODE_SIZE

// ---------------- scratch (static device globals; no allocation) ------------
__device__ __nv_bfloat16 g_a_hi [N_GRAPHS * INPUT_SIZE];       // GEMM1 A split
__device__ __nv_bfloat16 g_a_lo [N_GRAPHS * INPUT_SIZE];
__device__ __nv_bfloat16 g_h_hi [N_GRAPHS * HIDDEN_SIZE];      // GEMM2 A split
__device__ __nv_bfloat16 g_h_lo [N_GRAPHS * HIDDEN_SIZE];
__device__ __nv_bfloat16 g_w1t_hi[HIDDEN_SIZE * INPUT_SIZE];   // W1^T split [N,K]
__device__ __nv_bfloat16 g_w1t_lo[HIDDEN_SIZE * INPUT_SIZE];
__device__ __nv_bfloat16 g_w2t_hi[GLOBAL_SIZE * HIDDEN_SIZE];  // W2^T split [N,K]
__device__ __nv_bfloat16 g_w2t_lo[GLOBAL_SIZE * HIDDEN_SIZE];

// ================= helpers ====================================================
__device__ __forceinline__ uint32_t smem_u32(const void* p) {
    uint32_t a;
    asm("{ .reg .u64 t; cvta.to.shared.u64 t, %1; cvt.u32.u64 %0, t; }"
        : "=r"(a) : "l"(p));
    return a;
}
#define SW128(o) ((o) ^ (((o) >> 3) & 0x70))

__device__ __forceinline__ void ldsm_x4(uint32_t* r, uint32_t addr) {
    asm volatile("ldmatrix.sync.aligned.m8n8.x4.shared.b16 {%0,%1,%2,%3}, [%4];"
                 : "=r"(r[0]), "=r"(r[1]), "=r"(r[2]), "=r"(r[3]) : "r"(addr));
}

__device__ __forceinline__ void mma_bf16(float* c, const uint32_t* a,
                                         const uint32_t* b) {
    asm volatile(
        "mma.sync.aligned.m16n8k16.row.col.f32.bf16.bf16.f32 "
        "{%0,%1,%2,%3}, {%4,%5,%6,%7}, {%8,%9}, {%0,%1,%2,%3};"
        : "+f"(c[0]), "+f"(c[1]), "+f"(c[2]), "+f"(c[3])
        : "r"(a[0]), "r"(a[1]), "r"(a[2]), "r"(a[3]), "r"(b[0]), "r"(b[1]));
}

__device__ __forceinline__ void cp16(uint32_t s, const void* g) {
    asm volatile("cp.async.cg.shared.global [%0], [%1], 16;" :: "r"(s), "l"(g));
}
__device__ __forceinline__ void cp_commit() {
    asm volatile("cp.async.commit_group;" ::: "memory");
}
template <int N>
__device__ __forceinline__ void cp_wait() {
    asm volatile("cp.async.wait_group %0;" :: "n"(N) : "memory");
}

// ---------------- bf16 split helpers ------------------------------------------
__device__ __forceinline__ void split_bf16(float v, __nv_bfloat16& h, __nv_bfloat16& l) {
    h = __float2bfloat16(v);
    l = __float2bfloat16(v - __bfloat162float(h));
}

// streaming float4 load (evict-first; x is a 1GB single-use stream)
__device__ __forceinline__ float4 ldcs4(const float* p) {
    float4 v;
    asm volatile("ld.global.cs.v4.f32 {%0,%1,%2,%3}, [%4];"
                 : "=f"(v.x), "=f"(v.y), "=f"(v.z), "=f"(v.w) : "l"(p));
    return v;
}

// ---------------- kernel 1: fused segment-mean + concat + bf16 split ---------
// One CTA per graph. batch is sorted ascending -> binary search row range.
__global__ __launch_bounds__(128) void mean_split(
    const float* __restrict__ x, const int* __restrict__ batch,
    const float* __restrict__ u, int n)
{
    const int g = blockIdx.x;

    int l = 0, r = n;
    while (l < r) { int m = (l + r) >> 1; if (__ldg(&batch[m]) < g) l = m + 1; else r = m; }
    const int lo = l;
    r = n;
    while (l < r) { int m = (l + r) >> 1; if (__ldg(&batch[m]) < g + 1) l = m + 1; else r = m; }
    const int hi = l;

    const int c = threadIdx.x * 4;           // 128 threads x 4 = 512 cols
    float4 acc = make_float4(0.f, 0.f, 0.f, 0.f);

    int rr = lo;
    for (; rr + 8 <= hi; rr += 8) {          // 8-row unroll -> MLP=8
        float4 v0 = ldcs4(x + (size_t)(rr + 0) * NODE_SIZE + c);
        float4 v1 = ldcs4(x + (size_t)(rr + 1) * NODE_SIZE + c);
        float4 v2 = ldcs4(x + (size_t)(rr + 2) * NODE_SIZE + c);
        float4 v3 = ldcs4(x + (size_t)(rr + 3) * NODE_SIZE + c);
        float4 v4 = ldcs4(x + (size_t)(rr + 4) * NODE_SIZE + c);
        float4 v5 = ldcs4(x + (size_t)(rr + 5) * NODE_SIZE + c);
        float4 v6 = ldcs4(x + (size_t)(rr + 6) * NODE_SIZE + c);
        float4 v7 = ldcs4(x + (size_t)(rr + 7) * NODE_SIZE + c);
        acc.x += ((v0.x + v1.x) + (v2.x + v3.x)) + ((v4.x + v5.x) + (v6.x + v7.x));
        acc.y += ((v0.y + v1.y) + (v2.y + v3.y)) + ((v4.y + v5.y) + (v6.y + v7.y));
        acc.z += ((v0.z + v1.z) + (v2.z + v3.z)) + ((v4.z + v5.z) + (v6.z + v7.z));
        acc.w += ((v0.w + v1.w) + (v2.w + v3.w)) + ((v4.w + v5.w) + (v6.w + v7.w));
    }
    for (; rr < hi; ++rr) {
        float4 v = ldcs4(x + (size_t)rr * NODE_SIZE + c);
        acc.x += v.x; acc.y += v.y; acc.z += v.z; acc.w += v.w;
    }

    const float inv = 1.f / fmaxf((float)(hi - lo), 1.f);
    const size_t rowo = (size_t)g * INPUT_SIZE;

    {
        float4 v = make_float4(acc.x * inv, acc.y * inv, acc.z * inv, acc.w * inv);
        __nv_bfloat16 hx, hy, hz, hw, lx, ly, lz, lw;
        split_bf16(v.x, hx, lx); split_bf16(v.y, hy, ly);
        split_bf16(v.z, hz, lz); split_bf16(v.w, hw, lw);
        size_t o = rowo + GLOBAL_SIZE + c;
        *reinterpret_cast<__nv_bfloat162*>(&g_a_hi[o])     = __nv_bfloat162(hx, hy);
        *reinterpret_cast<__nv_bfloat162*>(&g_a_hi[o + 2]) = __nv_bfloat162(hz, hw);
        *reinterpret_cast<__nv_bfloat162*>(&g_a_lo[o])     = __nv_bfloat162(lx, ly);
        *reinterpret_cast<__nv_bfloat162*>(&g_a_lo[o + 2]) = __nv_bfloat162(lz, lw);
    }
    if (threadIdx.x < 64) {
        float4 v = *(const float4*)(u + (size_t)g * GLOBAL_SIZE + c);
        __nv_bfloat16 hx, hy, hz, hw, lx, ly, lz, lw;
        split_bf16(v.x, hx, lx); split_bf16(v.y, hy, ly);
        split_bf16(v.z, hz, lz); split_bf16(v.w, hw, lw);
        size_t o = rowo + c;
        *reinterpret_cast<__nv_bfloat162*>(&g_a_hi[o])     = __nv_bfloat162(hx, hy);
        *reinterpret_cast<__nv_bfloat162*>(&g_a_hi[o + 2]) = __nv_bfloat162(hz, hw);
        *reinterpret_cast<__nv_bfloat162*>(&g_a_lo[o])     = __nv_bfloat162(lx, ly);
        *reinterpret_cast<__nv_bfloat162*>(&g_a_lo[o + 2]) = __nv_bfloat162(lz, lw);
    }
}

// ---------------- kernel 2: transpose + split weights: W[K,N] -> Bt[N,K] -----
__global__ __launch_bounds__(256) void wsplit(
    const float* __restrict__ W, __nv_bfloat16* __restrict__ Bth,
    __nv_bfloat16* __restrict__ Btl, int K, int N)
{
    __shared__ float t[32][33];
    int k0 = blockIdx.x * 32, n0 = blockIdx.y * 32;
    int tx = threadIdx.x % 32, ty = threadIdx.x / 32;
    #pragma unroll
    for (int i = 0; i < 32; i += 8)
        t[ty + i][tx] = W[(size_t)(k0 + ty + i) * N + n0 + tx];
    __syncthreads();
    #pragma unroll
    for (int i = 0; i < 32; i += 8) {
        float v = t[tx][ty + i];
        __nv_bfloat16 h, l; split_bf16(v, h, l);
        size_t o = (size_t)(n0 + ty + i) * K + k0 + tx;
        Bth[o] = h; Btl[o] = l;
    }
}

// ---------------- SELU --------------------------------------------------------
__device__ __forceinline__ float selu_f(float v) {
    const float scale = 1.0507009873554805f;
    const float alpha = 1.6732632423543772f;
    return v > 0.f ? scale * v : scale * alpha * (expf(v) - 1.f);
}

// ================= mma.sync bf16x3 GEMM, cp.async double-buffered =============
// C[M,N] = act(A @ Bt^T + bias). A=[M,K] bf16 hi/lo, Bt=[N,K] bf16 hi/lo.
// 3-term split: AhBh + AhBl + AlBh, fp32 accum (rel err ~2^-18).
// Small 64x64 tiles + MINCTA CTAs/SM so warp count covers ldsm->mma latency.
template <int BM, int BN, int KTOT, int WM, int WN, int MINCTA, bool ACT, bool SPLIT>
__global__ void __launch_bounds__(256, MINCTA) mma_gemm(
    const __nv_bfloat16* __restrict__ Ah, const __nv_bfloat16* __restrict__ Al,
    const __nv_bfloat16* __restrict__ Bh, const __nv_bfloat16* __restrict__ Bl,
    const float* __restrict__ bias,
    float* __restrict__ Cf, __nv_bfloat16* __restrict__ Ch,
    __nv_bfloat16* __restrict__ Cl, int Ntot)
{
    constexpr int KC  = 64;          // K elements per smem stage
    constexpr int RB  = 128;         // bytes per smem row (KC * 2)
    constexpr int WGM = BM / WM;     // warps along M
    constexpr int MT  = WM / 16;
    constexpr int NT  = WN / 8;
    constexpr int STAGE = 2 * BM * RB + 2 * BN * RB;
    static_assert((BM / WM) * (BN / WN) == 8, "8 warps");
    static_assert(NT % 2 == 0, "B ldmatrix.x4 covers 2 n-tiles");

    extern __shared__ char dsm[];
    uint32_t raw = smem_u32(dsm);
    uint32_t sb  = (raw + 1023u) & ~1023u;
    char* base   = dsm + (sb - raw);

    float* biass = (float*)base;     // [BN] floats in first 1024B
    uint32_t AHIa[2], ALOa[2], BHIa[2], BLOa[2];
    #pragma unroll
    for (int s = 0; s < 2; ++s) {
        uint32_t b0 = sb + 1024 + s * STAGE;
        AHIa[s] = b0;
        ALOa[s] = b0 + BM * RB;
        BHIa[s] = b0 + 2 * BM * RB;
        BLOa[s] = b0 + 2 * BM * RB + BN * RB;
    }

    const int tid  = threadIdx.x;
    const int wid  = tid >> 5;
    const int lane = tid & 31;
    const int bm0  = blockIdx.y * BM;
    const int bn0  = blockIdx.x * BN;
    const int wm0  = (wid % WGM) * WM;
    const int wn0  = (wid / WGM) * WN;

    for (int i = tid; i < BN; i += 256) biass[i] = bias[bn0 + i];

    float acc[MT][NT][4];
    #pragma unroll
    for (int i = 0; i < MT; ++i)
        #pragma unroll
        for (int j = 0; j < NT; ++j)
            #pragma unroll
            for (int q = 0; q < 4; ++q) acc[i][j][q] = 0.f;

    constexpr int A_IT = BM * 8 / 256;
    constexpr int B_IT = BN * 8 / 256;

    auto load_stage = [&](int kcc, int s) {
        const int kel = kcc * KC;
        #pragma unroll
        for (int i = 0; i < A_IT; ++i) {
            int e = tid + i * 256;
            int row = e >> 3, seg = e & 7;
            uint32_t so = SW128((uint32_t)(row * RB + seg * 16));
            size_t ga = (size_t)(bm0 + row) * KTOT + kel + seg * 8;
            cp16(AHIa[s] + so, Ah + ga);
            cp16(ALOa[s] + so, Al + ga);
        }
        #pragma unroll
        for (int i = 0; i < B_IT; ++i) {
            int e = tid + i * 256;
            int row = e >> 3, seg = e & 7;
            uint32_t so = SW128((uint32_t)(row * RB + seg * 16));
            size_t gb = (size_t)(bn0 + row) * KTOT + kel + seg * 8;
            cp16(BHIa[s] + so, Bh + gb);
            cp16(BLOa[s] + so, Bl + gb);
        }
        cp_commit();
    };

    const int g  = lane >> 3;
    const int lr = lane & 7;
    const uint32_t a_row_off = (uint32_t)(wm0 + (g & 1) * 8 + lr) * RB + (uint32_t)(g >> 1) * 16;
    const uint32_t b_row_off = (uint32_t)(wn0 + (g >> 1) * 8 + lr) * RB + (uint32_t)(g & 1) * 16;

    constexpr int NCH = KTOT / KC;
    load_stage(0, 0);

    for (int kc = 0; kc < NCH; ++kc) {
        const int buf = kc & 1;
        if (kc + 1 < NCH) {
            load_stage(kc + 1, buf ^ 1);
            cp_wait<1>();
        } else {
            cp_wait<0>();
        }
        __syncthreads();

        const uint32_t AHIb = AHIa[buf], ALOb = ALOa[buf];
        const uint32_t BHIb = BHIa[buf], BLOb = BLOa[buf];

        #pragma unroll
        for (int ks = 0; ks < 4; ++ks) {
            const uint32_t kb = (uint32_t)ks * 32;

            uint32_t a_hi[MT][4], a_lo[MT][4];
            #pragma unroll
            for (int mt = 0; mt < MT; ++mt) {
                uint32_t off = a_row_off + (uint32_t)mt * 16 * RB + kb;
                ldsm_x4(a_hi[mt], AHIb + SW128(off));
                ldsm_x4(a_lo[mt], ALOb + SW128(off));
            }
            uint32_t b_hi[NT][2], b_lo[NT][2];
            #pragma unroll
            for (int np = 0; np < NT / 2; ++np) {
                uint32_t off = b_row_off + (uint32_t)np * 16 * RB + kb;
                uint32_t th[4], tl[4];
                ldsm_x4(th, BHIb + SW128(off));
                ldsm_x4(tl, BLOb + SW128(off));
                b_hi[np * 2][0] = th[0]; b_hi[np * 2][1] = th[1];
                b_hi[np * 2 + 1][0] = th[2]; b_hi[np * 2 + 1][1] = th[3];
                b_lo[np * 2][0] = tl[0]; b_lo[np * 2][1] = tl[1];
                b_lo[np * 2 + 1][0] = tl[2]; b_lo[np * 2 + 1][1] = tl[3];
            }
            #pragma unroll
            for (int mt = 0; mt < MT; ++mt)
                #pragma unroll
                for (int nt = 0; nt < NT; ++nt) {
                    mma_bf16(acc[mt][nt], a_hi[mt], b_hi[nt]);
                    mma_bf16(acc[mt][nt], a_hi[mt], b_lo[nt]);
                    mma_bf16(acc[mt][nt], a_lo[mt], b_hi[nt]);
                }
        }
        __syncthreads();
    }

    // ---- epilogue: bias + act, write out ----
    const int er = lane >> 2;
    const int ec = (lane & 3) * 2;
    #pragma unroll
    for (int mt = 0; mt < MT; ++mt) {
        #pragma unroll
        for (int nt = 0; nt < NT; ++nt) {
            int col = wn0 + nt * 8 + ec;
            float bx = biass[col], by = biass[col + 1];
            float v0 = acc[mt][nt][0] + bx, v1 = acc[mt][nt][1] + by;
            float v2 = acc[mt][nt][2] + bx, v3 = acc[mt][nt][3] + by;
            if (ACT) { v0 = selu_f(v0); v1 = selu_f(v1); v2 = selu_f(v2); v3 = selu_f(v3); }
            size_t r0 = (size_t)(bm0 + wm0 + mt * 16 + er);
            size_t r1 = r0 + 8;
            size_t o0 = r0 * Ntot + bn0 + col;
            size_t o1 = r1 * Ntot + bn0 + col;
            if (SPLIT) {
                __nv_bfloat16 h0, l0, h1, l1, h2, l2, h3, l3;
                split_bf16(v0, h0, l0); split_bf16(v1, h1, l1);
                split_bf16(v2, h2, l2); split_bf16(v3, h3, l3);
                *reinterpret_cast<__nv_bfloat162*>(&Ch[o0]) = __nv_bfloat162(h0, h1);
                *reinterpret_cast<__nv_bfloat162*>(&Cl[o0]) = __nv_bfloat162(l0, l1);
                *reinterpret_cast<__nv_bfloat162*>(&Ch[o1]) = __nv_bfloat162(h2, h3);
                *reinterpret_cast<__nv_bfloat162*>(&Cl[o1]) = __nv_bfloat162(l2, l3);
            } else {
                *reinterpret_cast<float2*>(&Cf[o0]) = make_float2(v0, v1);
                *reinterpret_cast<float2*>(&Cf[o1]) = make_float2(v2, v3);
            }
        }
    }
}

// ---------------- launch ------------------------------------------------------
extern "C" void kernel_launch(void* const* d_in, const int* in_sizes, int n_in,
                              void* d_out, int out_size)
{
    const float* x     = (const float*)d_in[0];
    // d_in[1] = edge_index (unused), d_in[2] = edge_attr (unused)
    const float* u     = (const float*)d_in[3];
    const int*   batch = (const int*)d_in[4];
    const float* W1    = (const float*)d_in[5];
    const float* b1    = (const float*)d_in[6];
    const float* W2    = (const float*)d_in[7];
    const float* b2    = (const float*)d_in[8];
    float*       out   = (float*)d_out;

    const int n_nodes = in_sizes[0] / NODE_SIZE;

    void *p_ah, *p_al, *p_hh, *p_hl, *p_w1h, *p_w1l, *p_w2h, *p_w2l;
    cudaGetSymbolAddress(&p_ah,  g_a_hi);   cudaGetSymbolAddress(&p_al,  g_a_lo);
    cudaGetSymbolAddress(&p_hh,  g_h_hi);   cudaGetSymbolAddress(&p_hl,  g_h_lo);
    cudaGetSymbolAddress(&p_w1h, g_w1t_hi); cudaGetSymbolAddress(&p_w1l, g_w1t_lo);
    cudaGetSymbolAddress(&p_w2h, g_w2t_hi); cudaGetSymbolAddress(&p_w2l, g_w2t_lo);

    // 64x64 tiles: smem = 1024 + 2*(2*64*128 + 2*64*128) = 66560 B -> 3 CTAs/SM
    constexpr int SMB = 1024 + 2 * (2 * 64 * 128 + 2 * 64 * 128);
    cudaFuncSetAttribute(
        (const void*)mma_gemm<64, 64, INPUT_SIZE, 16, 32, 3, true, true>,
        cudaFuncAttributeMaxDynamicSharedMemorySize, SMB);
    cudaFuncSetAttribute(
        (const void*)mma_gemm<64, 64, HIDDEN_SIZE, 16, 32, 3, false, false>,
        cudaFuncAttributeMaxDynamicSharedMemorySize, SMB);

    // weight transpose+split (small)
    wsplit<<<dim3(INPUT_SIZE / 32, HIDDEN_SIZE / 32), 256>>>(
        W1, (__nv_bfloat16*)p_w1h, (__nv_bfloat16*)p_w1l, INPUT_SIZE, HIDDEN_SIZE);
    wsplit<<<dim3(HIDDEN_SIZE / 32, GLOBAL_SIZE / 32), 256>>>(
        W2, (__nv_bfloat16*)p_w2h, (__nv_bfloat16*)p_w2l, HIDDEN_SIZE, GLOBAL_SIZE);

    // fused segment-mean + concat + split (the HBM-bound pass over x)
    mean_split<<<N_GRAPHS, 128>>>(x, batch, u, n_nodes);

    // GEMM1: [4096,768] @ [768,1024] + b1, SELU -> g_h hi/lo (bf16 split out)
    mma_gemm<64, 64, INPUT_SIZE, 16, 32, 3, true, true>
        <<<dim3(HIDDEN_SIZE / 64, N_GRAPHS / 64), 256, SMB>>>(
            (const __nv_bfloat16*)p_ah, (const __nv_bfloat16*)p_al,
            (const __nv_bfloat16*)p_w1h, (const __nv_bfloat16*)p_w1l,
            b1, nullptr, (__nv_bfloat16*)p_hh, (__nv_bfloat16*)p_hl, HIDDEN_SIZE);

    // GEMM2: [4096,1024] @ [1024,256] + b2 -> out (fp32)
    mma_gemm<64, 64, HIDDEN_SIZE, 16, 32, 3, false, false>
        <<<dim3(GLOBAL_SIZE / 64, N_GRAPHS / 64), 256, SMB>>>(
            (const __nv_bfloat16*)p_hh, (const __nv_bfloat16*)p_hl,
            (const __nv_bfloat16*)p_w2h, (const __nv_bfloat16*)p_w2l,
            b2, out, nullptr, nullptr, GLOBAL_SIZE);
}

// round 9
// speedup vs baseline: 1.9529x; 1.1098x over previous
#include <cuda_runtime.h>
#include <cuda_fp16.h>
#include <math.h>
#include <stdint.h>

#define N_GRAPHS 4096
#define NODE_SIZE 512
#define GLOBAL_SIZE 256
#define HIDDEN_SIZE 1024
#define INPUT_SIZE 768   // GLOBAL_SIZE + NODE_SIZE

// ---------------- scratch (static device globals; no allocation) ------------
__device__ __half g_a_hi[N_GRAPHS * INPUT_SIZE];        // GEMM1 A fp16 split
__device__ __half g_a_lo[N_GRAPHS * INPUT_SIZE];
__device__ __half g_h_hi[N_GRAPHS * HIDDEN_SIZE];       // GEMM2 A fp16 split
__device__ __half g_h_lo[N_GRAPHS * HIDDEN_SIZE];
__device__ __half g_w1t [HIDDEN_SIZE * INPUT_SIZE];     // W1^T fp16 [N,K]
__device__ __half g_w2t [GLOBAL_SIZE * HIDDEN_SIZE];    // W2^T fp16 [N,K]

// ================= helpers ====================================================
__device__ __forceinline__ uint32_t smem_u32(const void* p) {
    uint32_t a;
    asm("{ .reg .u64 t; cvta.to.shared.u64 t, %1; cvt.u32.u64 %0, t; }"
        : "=r"(a) : "l"(p));
    return a;
}
#define SW128(o) ((o) ^ (((o) >> 3) & 0x70))

__device__ __forceinline__ void ldsm_x4(uint32_t* r, uint32_t addr) {
    asm volatile("ldmatrix.sync.aligned.m8n8.x4.shared.b16 {%0,%1,%2,%3}, [%4];"
                 : "=r"(r[0]), "=r"(r[1]), "=r"(r[2]), "=r"(r[3]) : "r"(addr));
}

__device__ __forceinline__ void mma_f16(float* c, const uint32_t* a,
                                        const uint32_t* b) {
    asm volatile(
        "mma.sync.aligned.m16n8k16.row.col.f32.f16.f16.f32 "
        "{%0,%1,%2,%3}, {%4,%5,%6,%7}, {%8,%9}, {%0,%1,%2,%3};"
        : "+f"(c[0]), "+f"(c[1]), "+f"(c[2]), "+f"(c[3])
        : "r"(a[0]), "r"(a[1]), "r"(a[2]), "r"(a[3]), "r"(b[0]), "r"(b[1]));
}

__device__ __forceinline__ void cp16(uint32_t s, const void* g) {
    asm volatile("cp.async.cg.shared.global [%0], [%1], 16;" :: "r"(s), "l"(g));
}
__device__ __forceinline__ void cp_commit() {
    asm volatile("cp.async.commit_group;" ::: "memory");
}
template <int N>
__device__ __forceinline__ void cp_wait() {
    asm volatile("cp.async.wait_group %0;" :: "n"(N) : "memory");
}

// ---------------- fp16 split helpers -----------------------------------------
__device__ __forceinline__ void split_f16(float v, __half& h, __half& l) {
    h = __float2half_rn(v);
    l = __float2half_rn(v - __half2float(h));
}

// streaming float4 load (evict-first; x is a 1GB single-use stream)
__device__ __forceinline__ float4 ldcs4(const float* p) {
    float4 v;
    asm volatile("ld.global.cs.v4.f32 {%0,%1,%2,%3}, [%4];"
                 : "=f"(v.x), "=f"(v.y), "=f"(v.z), "=f"(v.w) : "l"(p));
    return v;
}

// ---------------- kernel 1: fused segment-mean + concat + fp16 split ---------
// One CTA per graph. batch is sorted ascending -> binary search row range.
__global__ __launch_bounds__(128) void mean_split(
    const float* __restrict__ x, const int* __restrict__ batch,
    const float* __restrict__ u, int n)
{
    const int g = blockIdx.x;

    int l = 0, r = n;
    while (l < r) { int m = (l + r) >> 1; if (__ldg(&batch[m]) < g) l = m + 1; else r = m; }
    const int lo = l;
    r = n;
    while (l < r) { int m = (l + r) >> 1; if (__ldg(&batch[m]) < g + 1) l = m + 1; else r = m; }
    const int hi = l;

    const int c = threadIdx.x * 4;           // 128 threads x 4 = 512 cols
    float4 acc = make_float4(0.f, 0.f, 0.f, 0.f);

    int rr = lo;
    for (; rr + 8 <= hi; rr += 8) {          // 8-row unroll -> MLP=8
        float4 v0 = ldcs4(x + (size_t)(rr + 0) * NODE_SIZE + c);
        float4 v1 = ldcs4(x + (size_t)(rr + 1) * NODE_SIZE + c);
        float4 v2 = ldcs4(x + (size_t)(rr + 2) * NODE_SIZE + c);
        float4 v3 = ldcs4(x + (size_t)(rr + 3) * NODE_SIZE + c);
        float4 v4 = ldcs4(x + (size_t)(rr + 4) * NODE_SIZE + c);
        float4 v5 = ldcs4(x + (size_t)(rr + 5) * NODE_SIZE + c);
        float4 v6 = ldcs4(x + (size_t)(rr + 6) * NODE_SIZE + c);
        float4 v7 = ldcs4(x + (size_t)(rr + 7) * NODE_SIZE + c);
        acc.x += ((v0.x + v1.x) + (v2.x + v3.x)) + ((v4.x + v5.x) + (v6.x + v7.x));
        acc.y += ((v0.y + v1.y) + (v2.y + v3.y)) + ((v4.y + v5.y) + (v6.y + v7.y));
        acc.z += ((v0.z + v1.z) + (v2.z + v3.z)) + ((v4.z + v5.z) + (v6.z + v7.z));
        acc.w += ((v0.w + v1.w) + (v2.w + v3.w)) + ((v4.w + v5.w) + (v6.w + v7.w));
    }
    for (; rr < hi; ++rr) {
        float4 v = ldcs4(x + (size_t)rr * NODE_SIZE + c);
        acc.x += v.x; acc.y += v.y; acc.z += v.z; acc.w += v.w;
    }

    const float inv = 1.f / fmaxf((float)(hi - lo), 1.f);
    const size_t rowo = (size_t)g * INPUT_SIZE;

    {
        float4 v = make_float4(acc.x * inv, acc.y * inv, acc.z * inv, acc.w * inv);
        __half hx, hy, hz, hw, lx, ly, lz, lw;
        split_f16(v.x, hx, lx); split_f16(v.y, hy, ly);
        split_f16(v.z, hz, lz); split_f16(v.w, hw, lw);
        size_t o = rowo + GLOBAL_SIZE + c;
        *reinterpret_cast<__half2*>(&g_a_hi[o])     = __halves2half2(hx, hy);
        *reinterpret_cast<__half2*>(&g_a_hi[o + 2]) = __halves2half2(hz, hw);
        *reinterpret_cast<__half2*>(&g_a_lo[o])     = __halves2half2(lx, ly);
        *reinterpret_cast<__half2*>(&g_a_lo[o + 2]) = __halves2half2(lz, lw);
    }
    if (threadIdx.x < 64) {
        float4 v = *(const float4*)(u + (size_t)g * GLOBAL_SIZE + c);
        __half hx, hy, hz, hw, lx, ly, lz, lw;
        split_f16(v.x, hx, lx); split_f16(v.y, hy, ly);
        split_f16(v.z, hz, lz); split_f16(v.w, hw, lw);
        size_t o = rowo + c;
        *reinterpret_cast<__half2*>(&g_a_hi[o])     = __halves2half2(hx, hy);
        *reinterpret_cast<__half2*>(&g_a_hi[o + 2]) = __halves2half2(hz, hw);
        *reinterpret_cast<__half2*>(&g_a_lo[o])     = __halves2half2(lx, ly);
        *reinterpret_cast<__half2*>(&g_a_lo[o + 2]) = __halves2half2(lz, lw);
    }
}

// ---------------- kernel 2: transpose weights to fp16: W[K,N] -> Bt[N,K] -----
__global__ __launch_bounds__(256) void wsplit(
    const float* __restrict__ W, __half* __restrict__ Bt, int K, int N)
{
    __shared__ float t[32][33];
    int k0 = blockIdx.x * 32, n0 = blockIdx.y * 32;
    int tx = threadIdx.x % 32, ty = threadIdx.x / 32;
    #pragma unroll
    for (int i = 0; i < 32; i += 8)
        t[ty + i][tx] = W[(size_t)(k0 + ty + i) * N + n0 + tx];
    __syncthreads();
    #pragma unroll
    for (int i = 0; i < 32; i += 8) {
        Bt[(size_t)(n0 + ty + i) * K + k0 + tx] = __float2half_rn(t[tx][ty + i]);
    }
}

// ---------------- SELU --------------------------------------------------------
__device__ __forceinline__ float selu_f(float v) {
    const float scale = 1.0507009873554805f;
    const float alpha = 1.6732632423543772f;
    return v > 0.f ? scale * v : scale * alpha * (expf(v) - 1.f);
}

// ================= mma.sync fp16x2 GEMM, cp.async double-buffered =============
// C[M,N] = act(A @ Bt^T + bias). A=[M,K] fp16 hi/lo, Bt=[N,K] fp16.
// 2-term split: AhBh + AlBh, fp32 accum. Error = A*(B - fp16(B)) ~ 1.6e-4 L2-rel.
template <int BM, int BN, int KTOT, int WM, int WN, int MINCTA, bool ACT, bool SPLIT>
__global__ void __launch_bounds__(256, MINCTA) mma_gemm(
    const __half* __restrict__ Ah, const __half* __restrict__ Al,
    const __half* __restrict__ Bh,
    const float* __restrict__ bias,
    float* __restrict__ Cf, __half* __restrict__ Ch,
    __half* __restrict__ Cl, int Ntot)
{
    constexpr int KC  = 64;          // K elements per smem stage
    constexpr int RB  = 128;         // bytes per smem row (KC * 2)
    constexpr int WGM = BM / WM;     // warps along M
    constexpr int MT  = WM / 16;
    constexpr int NT  = WN / 8;
    constexpr int STAGE = (2 * BM + BN) * RB;
    static_assert((BM / WM) * (BN / WN) == 8, "8 warps");
    static_assert(NT % 2 == 0, "B ldmatrix.x4 covers 2 n-tiles");

    extern __shared__ char dsm[];
    uint32_t raw = smem_u32(dsm);
    uint32_t sb  = (raw + 1023u) & ~1023u;
    char* base   = dsm + (sb - raw);

    float* biass = (float*)base;     // [BN] floats in first 1024B
    uint32_t AHIa[2], ALOa[2], BHIa[2];
    #pragma unroll
    for (int s = 0; s < 2; ++s) {
        uint32_t b0 = sb + 1024 + s * STAGE;
        AHIa[s] = b0;
        ALOa[s] = b0 + BM * RB;
        BHIa[s] = b0 + 2 * BM * RB;
    }

    const int tid  = threadIdx.x;
    const int wid  = tid >> 5;
    const int lane = tid & 31;
    const int bm0  = blockIdx.y * BM;
    const int bn0  = blockIdx.x * BN;
    const int wm0  = (wid % WGM) * WM;
    const int wn0  = (wid / WGM) * WN;

    for (int i = tid; i < BN; i += 256) biass[i] = bias[bn0 + i];

    float acc[MT][NT][4];
    #pragma unroll
    for (int i = 0; i < MT; ++i)
        #pragma unroll
        for (int j = 0; j < NT; ++j)
            #pragma unroll
            for (int q = 0; q < 4; ++q) acc[i][j][q] = 0.f;

    constexpr int A_IT = BM * 8 / 256;
    constexpr int B_IT = BN * 8 / 256;

    auto load_stage = [&](int kcc, int s) {
        const int kel = kcc * KC;
        #pragma unroll
        for (int i = 0; i < A_IT; ++i) {
            int e = tid + i * 256;
            int row = e >> 3, seg = e & 7;
            uint32_t so = SW128((uint32_t)(row * RB + seg * 16));
            size_t ga = (size_t)(bm0 + row) * KTOT + kel + seg * 8;
            cp16(AHIa[s] + so, Ah + ga);
            cp16(ALOa[s] + so, Al + ga);
        }
        #pragma unroll
        for (int i = 0; i < B_IT; ++i) {
            int e = tid + i * 256;
            int row = e >> 3, seg = e & 7;
            uint32_t so = SW128((uint32_t)(row * RB + seg * 16));
            size_t gb = (size_t)(bn0 + row) * KTOT + kel + seg * 8;
            cp16(BHIa[s] + so, Bh + gb);
        }
        cp_commit();
    };

    const int g  = lane >> 3;
    const int lr = lane & 7;
    const uint32_t a_row_off = (uint32_t)(wm0 + (g & 1) * 8 + lr) * RB + (uint32_t)(g >> 1) * 16;
    const uint32_t b_row_off = (uint32_t)(wn0 + (g >> 1) * 8 + lr) * RB + (uint32_t)(g & 1) * 16;

    constexpr int NCH = KTOT / KC;
    load_stage(0, 0);

    for (int kc = 0; kc < NCH; ++kc) {
        const int buf = kc & 1;
        if (kc + 1 < NCH) {
            load_stage(kc + 1, buf ^ 1);
            cp_wait<1>();
        } else {
            cp_wait<0>();
        }
        __syncthreads();

        const uint32_t AHIb = AHIa[buf], ALOb = ALOa[buf], BHIb = BHIa[buf];

        #pragma unroll
        for (int ks = 0; ks < 4; ++ks) {
            const uint32_t kb = (uint32_t)ks * 32;

            uint32_t a_hi[MT][4], a_lo[MT][4];
            #pragma unroll
            for (int mt = 0; mt < MT; ++mt) {
                uint32_t off = a_row_off + (uint32_t)mt * 16 * RB + kb;
                ldsm_x4(a_hi[mt], AHIb + SW128(off));
                ldsm_x4(a_lo[mt], ALOb + SW128(off));
            }
            uint32_t b_hi[NT][2];
            #pragma unroll
            for (int np = 0; np < NT / 2; ++np) {
                uint32_t off = b_row_off + (uint32_t)np * 16 * RB + kb;
                uint32_t th[4];
                ldsm_x4(th, BHIb + SW128(off));
                b_hi[np * 2][0] = th[0]; b_hi[np * 2][1] = th[1];
                b_hi[np * 2 + 1][0] = th[2]; b_hi[np * 2 + 1][1] = th[3];
            }
            // pass 1: hi terms (independent chains across nt)
            #pragma unroll
            for (int mt = 0; mt < MT; ++mt)
                #pragma unroll
                for (int nt = 0; nt < NT; ++nt)
                    mma_f16(acc[mt][nt], a_hi[mt], b_hi[nt]);
            // pass 2: lo correction
            #pragma unroll
            for (int mt = 0; mt < MT; ++mt)
                #pragma unroll
                for (int nt = 0; nt < NT; ++nt)
                    mma_f16(acc[mt][nt], a_lo[mt], b_hi[nt]);
        }
        __syncthreads();
    }

    // ---- epilogue: bias + act, write out ----
    const int er = lane >> 2;
    const int ec = (lane & 3) * 2;
    #pragma unroll
    for (int mt = 0; mt < MT; ++mt) {
        #pragma unroll
        for (int nt = 0; nt < NT; ++nt) {
            int col = wn0 + nt * 8 + ec;
            float bx = biass[col], by = biass[col + 1];
            float v0 = acc[mt][nt][0] + bx, v1 = acc[mt][nt][1] + by;
            float v2 = acc[mt][nt][2] + bx, v3 = acc[mt][nt][3] + by;
            if (ACT) { v0 = selu_f(v0); v1 = selu_f(v1); v2 = selu_f(v2); v3 = selu_f(v3); }
            size_t r0 = (size_t)(bm0 + wm0 + mt * 16 + er);
            size_t r1 = r0 + 8;
            size_t o0 = r0 * Ntot + bn0 + col;
            size_t o1 = r1 * Ntot + bn0 + col;
            if (SPLIT) {
                __half h0, l0, h1, l1, h2, l2, h3, l3;
                split_f16(v0, h0, l0); split_f16(v1, h1, l1);
                split_f16(v2, h2, l2); split_f16(v3, h3, l3);
                *reinterpret_cast<__half2*>(&Ch[o0]) = __halves2half2(h0, h1);
                *reinterpret_cast<__half2*>(&Cl[o0]) = __halves2half2(l0, l1);
                *reinterpret_cast<__half2*>(&Ch[o1]) = __halves2half2(h2, h3);
                *reinterpret_cast<__half2*>(&Cl[o1]) = __halves2half2(l2, l3);
            } else {
                *reinterpret_cast<float2*>(&Cf[o0]) = make_float2(v0, v1);
                *reinterpret_cast<float2*>(&Cf[o1]) = make_float2(v2, v3);
            }
        }
    }
}

// ---------------- launch ------------------------------------------------------
extern "C" void kernel_launch(void* const* d_in, const int* in_sizes, int n_in,
                              void* d_out, int out_size)
{
    const float* x     = (const float*)d_in[0];
    // d_in[1] = edge_index (unused), d_in[2] = edge_attr (unused)
    const float* u     = (const float*)d_in[3];
    const int*   batch = (const int*)d_in[4];
    const float* W1    = (const float*)d_in[5];
    const float* b1    = (const float*)d_in[6];
    const float* W2    = (const float*)d_in[7];
    const float* b2    = (const float*)d_in[8];
    float*       out   = (float*)d_out;

    const int n_nodes = in_sizes[0] / NODE_SIZE;

    void *p_ah, *p_al, *p_hh, *p_hl, *p_w1, *p_w2;
    cudaGetSymbolAddress(&p_ah, g_a_hi);  cudaGetSymbolAddress(&p_al, g_a_lo);
    cudaGetSymbolAddress(&p_hh, g_h_hi);  cudaGetSymbolAddress(&p_hl, g_h_lo);
    cudaGetSymbolAddress(&p_w1, g_w1t);   cudaGetSymbolAddress(&p_w2, g_w2t);

    // 64x64 tiles: smem = 1024 + 2*(2*64+64)*128 = 50176 B -> 3+ CTAs/SM
    constexpr int SMB = 1024 + 2 * (2 * 64 + 64) * 128;
    cudaFuncSetAttribute(
        (const void*)mma_gemm<64, 64, INPUT_SIZE, 16, 32, 3, true, true>,
        cudaFuncAttributeMaxDynamicSharedMemorySize, SMB);
    cudaFuncSetAttribute(
        (const void*)mma_gemm<64, 64, HIDDEN_SIZE, 16, 32, 3, false, false>,
        cudaFuncAttributeMaxDynamicSharedMemorySize, SMB);

    // weight transpose to fp16 (small)
    wsplit<<<dim3(INPUT_SIZE / 32, HIDDEN_SIZE / 32), 256>>>(
        W1, (__half*)p_w1, INPUT_SIZE, HIDDEN_SIZE);
    wsplit<<<dim3(HIDDEN_SIZE / 32, GLOBAL_SIZE / 32), 256>>>(
        W2, (__half*)p_w2, HIDDEN_SIZE, GLOBAL_SIZE);

    // fused segment-mean + concat + split (the HBM-bound pass over x)
    mean_split<<<N_GRAPHS, 128>>>(x, batch, u, n_nodes);

    // GEMM1: [4096,768] @ [768,1024] + b1, SELU -> g_h hi/lo (fp16 split out)
    mma_gemm<64, 64, INPUT_SIZE, 16, 32, 3, true, true>
        <<<dim3(HIDDEN_SIZE / 64, N_GRAPHS / 64), 256, SMB>>>(
            (const __half*)p_ah, (const __half*)p_al, (const __half*)p_w1,
            b1, nullptr, (__half*)p_hh, (__half*)p_hl, HIDDEN_SIZE);

    // GEMM2: [4096,1024] @ [1024,256] + b2 -> out (fp32)
    mma_gemm<64, 64, HIDDEN_SIZE, 16, 32, 3, false, false>
        <<<dim3(GLOBAL_SIZE / 64, N_GRAPHS / 64), 256, SMB>>>(
            (const __half*)p_hh, (const __half*)p_hl, (const __half*)p_w2,
            b2, out, nullptr, nullptr, GLOBAL_SIZE);
}

// round 10
// speedup vs baseline: 2.0789x; 1.0645x over previous
#include <cuda_runtime.h>
#include <cuda_fp16.h>
#include <math.h>
#include <stdint.h>

#define N_GRAPHS 4096
#define NODE_SIZE 512
#define GLOBAL_SIZE 256
#define HIDDEN_SIZE 1024
#define INPUT_SIZE 768   // GLOBAL_SIZE + NODE_SIZE

// ---------------- scratch (static device globals; no allocation) ------------
__device__ __half g_a   [N_GRAPHS * INPUT_SIZE];        // GEMM1 A fp16 (single)
__device__ __half g_h_hi[N_GRAPHS * HIDDEN_SIZE];       // GEMM2 A fp16 split
__device__ __half g_h_lo[N_GRAPHS * HIDDEN_SIZE];
__device__ __half g_w1t [HIDDEN_SIZE * INPUT_SIZE];     // W1^T fp16 [N,K]
__device__ __half g_w2t [GLOBAL_SIZE * HIDDEN_SIZE];    // W2^T fp16 [N,K]

// ================= helpers ====================================================
__device__ __forceinline__ uint32_t smem_u32(const void* p) {
    uint32_t a;
    asm("{ .reg .u64 t; cvta.to.shared.u64 t, %1; cvt.u32.u64 %0, t; }"
        : "=r"(a) : "l"(p));
    return a;
}
#define SW128(o) ((o) ^ (((o) >> 3) & 0x70))

__device__ __forceinline__ void ldsm_x4(uint32_t* r, uint32_t addr) {
    asm volatile("ldmatrix.sync.aligned.m8n8.x4.shared.b16 {%0,%1,%2,%3}, [%4];"
                 : "=r"(r[0]), "=r"(r[1]), "=r"(r[2]), "=r"(r[3]) : "r"(addr));
}

__device__ __forceinline__ void mma_f16(float* c, const uint32_t* a,
                                        const uint32_t* b) {
    asm volatile(
        "mma.sync.aligned.m16n8k16.row.col.f32.f16.f16.f32 "
        "{%0,%1,%2,%3}, {%4,%5,%6,%7}, {%8,%9}, {%0,%1,%2,%3};"
        : "+f"(c[0]), "+f"(c[1]), "+f"(c[2]), "+f"(c[3])
        : "r"(a[0]), "r"(a[1]), "r"(a[2]), "r"(a[3]), "r"(b[0]), "r"(b[1]));
}

__device__ __forceinline__ void cp16(uint32_t s, const void* g) {
    asm volatile("cp.async.cg.shared.global [%0], [%1], 16;" :: "r"(s), "l"(g));
}
__device__ __forceinline__ void cp_commit() {
    asm volatile("cp.async.commit_group;" ::: "memory");
}
template <int N>
__device__ __forceinline__ void cp_wait() {
    asm volatile("cp.async.wait_group %0;" :: "n"(N) : "memory");
}

// ---------------- fp16 split helpers -----------------------------------------
__device__ __forceinline__ void split_f16(float v, __half& h, __half& l) {
    h = __float2half_rn(v);
    l = __float2half_rn(v - __half2float(h));
}

// streaming float4 load (evict-first; x is a 1GB single-use stream)
__device__ __forceinline__ float4 ldcs4(const float* p) {
    float4 v;
    asm volatile("ld.global.cs.v4.f32 {%0,%1,%2,%3}, [%4];"
                 : "=f"(v.x), "=f"(v.y), "=f"(v.z), "=f"(v.w) : "l"(p));
    return v;
}

// ---------------- kernel 1: fused segment-mean + concat -> fp16 --------------
// One CTA per graph. batch is sorted ascending -> binary search row range.
__global__ __launch_bounds__(128) void mean_split(
    const float* __restrict__ x, const int* __restrict__ batch,
    const float* __restrict__ u, int n)
{
    const int g = blockIdx.x;

    int l = 0, r = n;
    while (l < r) { int m = (l + r) >> 1; if (__ldg(&batch[m]) < g) l = m + 1; else r = m; }
    const int lo = l;
    r = n;
    while (l < r) { int m = (l + r) >> 1; if (__ldg(&batch[m]) < g + 1) l = m + 1; else r = m; }
    const int hi = l;

    const int c = threadIdx.x * 4;           // 128 threads x 4 = 512 cols
    float4 acc = make_float4(0.f, 0.f, 0.f, 0.f);

    int rr = lo;
    for (; rr + 8 <= hi; rr += 8) {          // 8-row unroll -> MLP=8
        float4 v0 = ldcs4(x + (size_t)(rr + 0) * NODE_SIZE + c);
        float4 v1 = ldcs4(x + (size_t)(rr + 1) * NODE_SIZE + c);
        float4 v2 = ldcs4(x + (size_t)(rr + 2) * NODE_SIZE + c);
        float4 v3 = ldcs4(x + (size_t)(rr + 3) * NODE_SIZE + c);
        float4 v4 = ldcs4(x + (size_t)(rr + 4) * NODE_SIZE + c);
        float4 v5 = ldcs4(x + (size_t)(rr + 5) * NODE_SIZE + c);
        float4 v6 = ldcs4(x + (size_t)(rr + 6) * NODE_SIZE + c);
        float4 v7 = ldcs4(x + (size_t)(rr + 7) * NODE_SIZE + c);
        acc.x += ((v0.x + v1.x) + (v2.x + v3.x)) + ((v4.x + v5.x) + (v6.x + v7.x));
        acc.y += ((v0.y + v1.y) + (v2.y + v3.y)) + ((v4.y + v5.y) + (v6.y + v7.y));
        acc.z += ((v0.z + v1.z) + (v2.z + v3.z)) + ((v4.z + v5.z) + (v6.z + v7.z));
        acc.w += ((v0.w + v1.w) + (v2.w + v3.w)) + ((v4.w + v5.w) + (v6.w + v7.w));
    }
    for (; rr < hi; ++rr) {
        float4 v = ldcs4(x + (size_t)rr * NODE_SIZE + c);
        acc.x += v.x; acc.y += v.y; acc.z += v.z; acc.w += v.w;
    }

    const float inv = 1.f / fmaxf((float)(hi - lo), 1.f);
    const size_t rowo = (size_t)g * INPUT_SIZE;

    {
        size_t o = rowo + GLOBAL_SIZE + c;
        *reinterpret_cast<__half2*>(&g_a[o]) =
            __halves2half2(__float2half_rn(acc.x * inv), __float2half_rn(acc.y * inv));
        *reinterpret_cast<__half2*>(&g_a[o + 2]) =
            __halves2half2(__float2half_rn(acc.z * inv), __float2half_rn(acc.w * inv));
    }
    if (threadIdx.x < 64) {
        float4 v = *(const float4*)(u + (size_t)g * GLOBAL_SIZE + c);
        size_t o = rowo + c;
        *reinterpret_cast<__half2*>(&g_a[o]) =
            __halves2half2(__float2half_rn(v.x), __float2half_rn(v.y));
        *reinterpret_cast<__half2*>(&g_a[o + 2]) =
            __halves2half2(__float2half_rn(v.z), __float2half_rn(v.w));
    }
}

// ---------------- kernel 2: transpose weights to fp16: W[K,N] -> Bt[N,K] -----
__global__ __launch_bounds__(256) void wsplit(
    const float* __restrict__ W, __half* __restrict__ Bt, int K, int N)
{
    __shared__ float t[32][33];
    int k0 = blockIdx.x * 32, n0 = blockIdx.y * 32;
    int tx = threadIdx.x % 32, ty = threadIdx.x / 32;
    #pragma unroll
    for (int i = 0; i < 32; i += 8)
        t[ty + i][tx] = W[(size_t)(k0 + ty + i) * N + n0 + tx];
    __syncthreads();
    #pragma unroll
    for (int i = 0; i < 32; i += 8) {
        Bt[(size_t)(n0 + ty + i) * K + k0 + tx] = __float2half_rn(t[tx][ty + i]);
    }
}

// ---------------- SELU --------------------------------------------------------
__device__ __forceinline__ float selu_f(float v) {
    const float scale = 1.0507009873554805f;
    const float alpha = 1.6732632423543772f;
    return v > 0.f ? scale * v : scale * alpha * (expf(v) - 1.f);
}

// ================= mma.sync fp16 GEMM, cp.async double-buffered ===============
// C[M,N] = act(A @ Bt^T + bias). A=[M,K] fp16 (+optional lo plane), Bt=[N,K] fp16.
// ALO=true: 2-term split AhBh + AlBh (A exact to ~fp32); ALO=false: single-pass.
template <int BM, int BN, int KTOT, int WM, int WN, int MINCTA,
          bool ALO, bool ACT, bool SPLIT>
__global__ void __launch_bounds__(256, MINCTA) mma_gemm(
    const __half* __restrict__ Ah, const __half* __restrict__ Al,
    const __half* __restrict__ Bh,
    const float* __restrict__ bias,
    float* __restrict__ Cf, __half* __restrict__ Ch,
    __half* __restrict__ Cl, int Ntot)
{
    constexpr int KC  = 64;          // K elements per smem stage
    constexpr int RB  = 128;         // bytes per smem row (KC * 2)
    constexpr int WGM = BM / WM;     // warps along M
    constexpr int MT  = WM / 16;
    constexpr int NT  = WN / 8;
    constexpr int APL = ALO ? 2 : 1; // A planes
    constexpr int STAGE = (APL * BM + BN) * RB;
    static_assert((BM / WM) * (BN / WN) == 8, "8 warps");
    static_assert(NT % 2 == 0, "B ldmatrix.x4 covers 2 n-tiles");

    extern __shared__ char dsm[];
    uint32_t raw = smem_u32(dsm);
    uint32_t sb  = (raw + 1023u) & ~1023u;
    char* base   = dsm + (sb - raw);

    float* biass = (float*)base;     // [BN] floats in first 1024B
    uint32_t AHIa[2], ALOa[2], BHIa[2];
    #pragma unroll
    for (int s = 0; s < 2; ++s) {
        uint32_t b0 = sb + 1024 + s * STAGE;
        AHIa[s] = b0;
        ALOa[s] = b0 + BM * RB;                 // valid only if ALO
        BHIa[s] = b0 + APL * BM * RB;
    }

    const int tid  = threadIdx.x;
    const int wid  = tid >> 5;
    const int lane = tid & 31;
    const int bm0  = blockIdx.y * BM;
    const int bn0  = blockIdx.x * BN;
    const int wm0  = (wid % WGM) * WM;
    const int wn0  = (wid / WGM) * WN;

    for (int i = tid; i < BN; i += 256) biass[i] = bias[bn0 + i];

    float acc[MT][NT][4];
    #pragma unroll
    for (int i = 0; i < MT; ++i)
        #pragma unroll
        for (int j = 0; j < NT; ++j)
            #pragma unroll
            for (int q = 0; q < 4; ++q) acc[i][j][q] = 0.f;

    constexpr int A_IT = BM * 8 / 256;
    constexpr int B_IT = BN * 8 / 256;

    auto load_stage = [&](int kcc, int s) {
        const int kel = kcc * KC;
        #pragma unroll
        for (int i = 0; i < A_IT; ++i) {
            int e = tid + i * 256;
            int row = e >> 3, seg = e & 7;
            uint32_t so = SW128((uint32_t)(row * RB + seg * 16));
            size_t ga = (size_t)(bm0 + row) * KTOT + kel + seg * 8;
            cp16(AHIa[s] + so, Ah + ga);
            if (ALO) cp16(ALOa[s] + so, Al + ga);
        }
        #pragma unroll
        for (int i = 0; i < B_IT; ++i) {
            int e = tid + i * 256;
            int row = e >> 3, seg = e & 7;
            uint32_t so = SW128((uint32_t)(row * RB + seg * 16));
            size_t gb = (size_t)(bn0 + row) * KTOT + kel + seg * 8;
            cp16(BHIa[s] + so, Bh + gb);
        }
        cp_commit();
    };

    const int g  = lane >> 3;
    const int lr = lane & 7;
    const uint32_t a_row_off = (uint32_t)(wm0 + (g & 1) * 8 + lr) * RB + (uint32_t)(g >> 1) * 16;
    const uint32_t b_row_off = (uint32_t)(wn0 + (g >> 1) * 8 + lr) * RB + (uint32_t)(g & 1) * 16;

    constexpr int NCH = KTOT / KC;
    load_stage(0, 0);

    for (int kc = 0; kc < NCH; ++kc) {
        const int buf = kc & 1;
        if (kc + 1 < NCH) {
            load_stage(kc + 1, buf ^ 1);
            cp_wait<1>();
        } else {
            cp_wait<0>();
        }
        __syncthreads();

        const uint32_t AHIb = AHIa[buf], ALOb = ALOa[buf], BHIb = BHIa[buf];

        #pragma unroll
        for (int ks = 0; ks < 4; ++ks) {
            const uint32_t kb = (uint32_t)ks * 32;

            uint32_t a_hi[MT][4];
            #pragma unroll
            for (int mt = 0; mt < MT; ++mt)
                ldsm_x4(a_hi[mt], AHIb + SW128(a_row_off + (uint32_t)mt * 16 * RB + kb));
            uint32_t b_hi[NT][2];
            #pragma unroll
            for (int np = 0; np < NT / 2; ++np) {
                uint32_t th[4];
                ldsm_x4(th, BHIb + SW128(b_row_off + (uint32_t)np * 16 * RB + kb));
                b_hi[np * 2][0] = th[0]; b_hi[np * 2][1] = th[1];
                b_hi[np * 2 + 1][0] = th[2]; b_hi[np * 2 + 1][1] = th[3];
            }
            #pragma unroll
            for (int mt = 0; mt < MT; ++mt)
                #pragma unroll
                for (int nt = 0; nt < NT; ++nt)
                    mma_f16(acc[mt][nt], a_hi[mt], b_hi[nt]);

            if (ALO) {
                uint32_t a_lo[MT][4];
                #pragma unroll
                for (int mt = 0; mt < MT; ++mt)
                    ldsm_x4(a_lo[mt], ALOb + SW128(a_row_off + (uint32_t)mt * 16 * RB + kb));
                #pragma unroll
                for (int mt = 0; mt < MT; ++mt)
                    #pragma unroll
                    for (int nt = 0; nt < NT; ++nt)
                        mma_f16(acc[mt][nt], a_lo[mt], b_hi[nt]);
            }
        }
        __syncthreads();
    }

    // ---- epilogue: bias + act, write out ----
    const int er = lane >> 2;
    const int ec = (lane & 3) * 2;
    #pragma unroll
    for (int mt = 0; mt < MT; ++mt) {
        #pragma unroll
        for (int nt = 0; nt < NT; ++nt) {
            int col = wn0 + nt * 8 + ec;
            float bx = biass[col], by = biass[col + 1];
            float v0 = acc[mt][nt][0] + bx, v1 = acc[mt][nt][1] + by;
            float v2 = acc[mt][nt][2] + bx, v3 = acc[mt][nt][3] + by;
            if (ACT) { v0 = selu_f(v0); v1 = selu_f(v1); v2 = selu_f(v2); v3 = selu_f(v3); }
            size_t r0 = (size_t)(bm0 + wm0 + mt * 16 + er);
            size_t r1 = r0 + 8;
            size_t o0 = r0 * Ntot + bn0 + col;
            size_t o1 = r1 * Ntot + bn0 + col;
            if (SPLIT) {
                __half h0, l0, h1, l1, h2, l2, h3, l3;
                split_f16(v0, h0, l0); split_f16(v1, h1, l1);
                split_f16(v2, h2, l2); split_f16(v3, h3, l3);
                *reinterpret_cast<__half2*>(&Ch[o0]) = __halves2half2(h0, h1);
                *reinterpret_cast<__half2*>(&Cl[o0]) = __halves2half2(l0, l1);
                *reinterpret_cast<__half2*>(&Ch[o1]) = __halves2half2(h2, h3);
                *reinterpret_cast<__half2*>(&Cl[o1]) = __halves2half2(l2, l3);
            } else {
                *reinterpret_cast<float2*>(&Cf[o0]) = make_float2(v0, v1);
                *reinterpret_cast<float2*>(&Cf[o1]) = make_float2(v2, v3);
            }
        }
    }
}

// ---------------- launch ------------------------------------------------------
extern "C" void kernel_launch(void* const* d_in, const int* in_sizes, int n_in,
                              void* d_out, int out_size)
{
    const float* x     = (const float*)d_in[0];
    // d_in[1] = edge_index (unused), d_in[2] = edge_attr (unused)
    const float* u     = (const float*)d_in[3];
    const int*   batch = (const int*)d_in[4];
    const float* W1    = (const float*)d_in[5];
    const float* b1    = (const float*)d_in[6];
    const float* W2    = (const float*)d_in[7];
    const float* b2    = (const float*)d_in[8];
    float*       out   = (float*)d_out;

    const int n_nodes = in_sizes[0] / NODE_SIZE;

    void *p_a, *p_hh, *p_hl, *p_w1, *p_w2;
    cudaGetSymbolAddress(&p_a,  g_a);
    cudaGetSymbolAddress(&p_hh, g_h_hi); cudaGetSymbolAddress(&p_hl, g_h_lo);
    cudaGetSymbolAddress(&p_w1, g_w1t);  cudaGetSymbolAddress(&p_w2, g_w2t);

    // GEMM1 (ALO=0, 128x64): smem = 1024 + 2*(128+64)*128 = 50176
    // GEMM2 (ALO=1,  64x64): smem = 1024 + 2*(2*64+64)*128 = 50176
    constexpr int SMB = 1024 + 2 * 192 * 128;
    cudaFuncSetAttribute(
        (const void*)mma_gemm<128, 64, INPUT_SIZE, 32, 32, 3, false, true, true>,
        cudaFuncAttributeMaxDynamicSharedMemorySize, SMB);
    cudaFuncSetAttribute(
        (const void*)mma_gemm<64, 64, HIDDEN_SIZE, 16, 32, 3, true, false, false>,
        cudaFuncAttributeMaxDynamicSharedMemorySize, SMB);

    // weight transpose to fp16 (small)
    wsplit<<<dim3(INPUT_SIZE / 32, HIDDEN_SIZE / 32), 256>>>(
        W1, (__half*)p_w1, INPUT_SIZE, HIDDEN_SIZE);
    wsplit<<<dim3(HIDDEN_SIZE / 32, GLOBAL_SIZE / 32), 256>>>(
        W2, (__half*)p_w2, HIDDEN_SIZE, GLOBAL_SIZE);

    // fused segment-mean + concat (the HBM-bound pass over x)
    mean_split<<<N_GRAPHS, 128>>>(x, batch, u, n_nodes);

    // GEMM1: [4096,768] @ [768,1024] + b1, SELU -> g_h hi/lo (fp16 split out)
    // single-plane A (fp16), 128x64 tiles, WM=32 keeps ldsm/MMA at 0.5
    mma_gemm<128, 64, INPUT_SIZE, 32, 32, 3, false, true, true>
        <<<dim3(HIDDEN_SIZE / 64, N_GRAPHS / 128), 256, SMB>>>(
            (const __half*)p_a, nullptr, (const __half*)p_w1,
            b1, nullptr, (__half*)p_hh, (__half*)p_hl, HIDDEN_SIZE);

    // GEMM2: [4096,1024] @ [1024,256] + b2 -> out (fp32), 2-term A-split
    mma_gemm<64, 64, HIDDEN_SIZE, 16, 32, 3, true, false, false>
        <<<dim3(GLOBAL_SIZE / 64, N_GRAPHS / 64), 256, SMB>>>(
            (const __half*)p_hh, (const __half*)p_hl, (const __half*)p_w2,
            b2, out, nullptr, nullptr, GLOBAL_SIZE);
}

// round 11
// speedup vs baseline: 2.1594x; 1.0387x over previous
#include <cuda_runtime.h>
#include <cuda_fp16.h>
#include <math.h>
#include <stdint.h>

#define N_GRAPHS 4096
#define NODE_SIZE 512
#define GLOBAL_SIZE 256
#define HIDDEN_SIZE 1024
#define INPUT_SIZE 768   // GLOBAL_SIZE + NODE_SIZE

// ---------------- scratch (static device globals; no allocation) ------------
__device__ __half g_a  [N_GRAPHS * INPUT_SIZE];         // GEMM1 A fp16
__device__ __half g_h  [N_GRAPHS * HIDDEN_SIZE];        // GEMM2 A fp16
__device__ __half g_w1t[HIDDEN_SIZE * INPUT_SIZE];      // W1^T fp16 [N,K]
__device__ __half g_w2t[GLOBAL_SIZE * HIDDEN_SIZE];     // W2^T fp16 [N,K]

// ================= helpers ====================================================
__device__ __forceinline__ uint32_t smem_u32(const void* p) {
    uint32_t a;
    asm("{ .reg .u64 t; cvta.to.shared.u64 t, %1; cvt.u32.u64 %0, t; }"
        : "=r"(a) : "l"(p));
    return a;
}
#define SW128(o) ((o) ^ (((o) >> 3) & 0x70))

__device__ __forceinline__ void ldsm_x4(uint32_t* r, uint32_t addr) {
    asm volatile("ldmatrix.sync.aligned.m8n8.x4.shared.b16 {%0,%1,%2,%3}, [%4];"
                 : "=r"(r[0]), "=r"(r[1]), "=r"(r[2]), "=r"(r[3]) : "r"(addr));
}

__device__ __forceinline__ void mma_f16(float* c, const uint32_t* a,
                                        const uint32_t* b) {
    asm volatile(
        "mma.sync.aligned.m16n8k16.row.col.f32.f16.f16.f32 "
        "{%0,%1,%2,%3}, {%4,%5,%6,%7}, {%8,%9}, {%0,%1,%2,%3};"
        : "+f"(c[0]), "+f"(c[1]), "+f"(c[2]), "+f"(c[3])
        : "r"(a[0]), "r"(a[1]), "r"(a[2]), "r"(a[3]), "r"(b[0]), "r"(b[1]));
}

__device__ __forceinline__ void cp16(uint32_t s, const void* g) {
    asm volatile("cp.async.cg.shared.global [%0], [%1], 16;" :: "r"(s), "l"(g));
}
__device__ __forceinline__ void cp_commit() {
    asm volatile("cp.async.commit_group;" ::: "memory");
}
template <int N>
__device__ __forceinline__ void cp_wait() {
    asm volatile("cp.async.wait_group %0;" :: "n"(N) : "memory");
}

// streaming float4 load (evict-first; x is a 1GB single-use stream)
__device__ __forceinline__ float4 ldcs4(const float* p) {
    float4 v;
    asm volatile("ld.global.cs.v4.f32 {%0,%1,%2,%3}, [%4];"
                 : "=f"(v.x), "=f"(v.y), "=f"(v.z), "=f"(v.w) : "l"(p));
    return v;
}

// ---------------- kernel 1: fused segment-mean + concat -> fp16 --------------
// One CTA per graph. batch is sorted ascending -> binary search row range.
__global__ __launch_bounds__(128) void mean_split(
    const float* __restrict__ x, const int* __restrict__ batch,
    const float* __restrict__ u, int n)
{
    const int g = blockIdx.x;

    int l = 0, r = n;
    while (l < r) { int m = (l + r) >> 1; if (__ldg(&batch[m]) < g) l = m + 1; else r = m; }
    const int lo = l;
    r = n;
    while (l < r) { int m = (l + r) >> 1; if (__ldg(&batch[m]) < g + 1) l = m + 1; else r = m; }
    const int hi = l;

    const int c = threadIdx.x * 4;           // 128 threads x 4 = 512 cols
    float4 acc = make_float4(0.f, 0.f, 0.f, 0.f);

    int rr = lo;
    for (; rr + 8 <= hi; rr += 8) {          // 8-row unroll -> MLP=8
        float4 v0 = ldcs4(x + (size_t)(rr + 0) * NODE_SIZE + c);
        float4 v1 = ldcs4(x + (size_t)(rr + 1) * NODE_SIZE + c);
        float4 v2 = ldcs4(x + (size_t)(rr + 2) * NODE_SIZE + c);
        float4 v3 = ldcs4(x + (size_t)(rr + 3) * NODE_SIZE + c);
        float4 v4 = ldcs4(x + (size_t)(rr + 4) * NODE_SIZE + c);
        float4 v5 = ldcs4(x + (size_t)(rr + 5) * NODE_SIZE + c);
        float4 v6 = ldcs4(x + (size_t)(rr + 6) * NODE_SIZE + c);
        float4 v7 = ldcs4(x + (size_t)(rr + 7) * NODE_SIZE + c);
        acc.x += ((v0.x + v1.x) + (v2.x + v3.x)) + ((v4.x + v5.x) + (v6.x + v7.x));
        acc.y += ((v0.y + v1.y) + (v2.y + v3.y)) + ((v4.y + v5.y) + (v6.y + v7.y));
        acc.z += ((v0.z + v1.z) + (v2.z + v3.z)) + ((v4.z + v5.z) + (v6.z + v7.z));
        acc.w += ((v0.w + v1.w) + (v2.w + v3.w)) + ((v4.w + v5.w) + (v6.w + v7.w));
    }
    for (; rr < hi; ++rr) {
        float4 v = ldcs4(x + (size_t)rr * NODE_SIZE + c);
        acc.x += v.x; acc.y += v.y; acc.z += v.z; acc.w += v.w;
    }

    const float inv = 1.f / fmaxf((float)(hi - lo), 1.f);
    const size_t rowo = (size_t)g * INPUT_SIZE;

    {
        size_t o = rowo + GLOBAL_SIZE + c;
        *reinterpret_cast<__half2*>(&g_a[o]) =
            __halves2half2(__float2half_rn(acc.x * inv), __float2half_rn(acc.y * inv));
        *reinterpret_cast<__half2*>(&g_a[o + 2]) =
            __halves2half2(__float2half_rn(acc.z * inv), __float2half_rn(acc.w * inv));
    }
    if (threadIdx.x < 64) {
        float4 v = *(const float4*)(u + (size_t)g * GLOBAL_SIZE + c);
        size_t o = rowo + c;
        *reinterpret_cast<__half2*>(&g_a[o]) =
            __halves2half2(__float2half_rn(v.x), __float2half_rn(v.y));
        *reinterpret_cast<__half2*>(&g_a[o + 2]) =
            __halves2half2(__float2half_rn(v.z), __float2half_rn(v.w));
    }
}

// ---------------- kernel 2: transpose weights to fp16: W[K,N] -> Bt[N,K] -----
__global__ __launch_bounds__(256) void wsplit(
    const float* __restrict__ W, __half* __restrict__ Bt, int K, int N)
{
    __shared__ float t[32][33];
    int k0 = blockIdx.x * 32, n0 = blockIdx.y * 32;
    int tx = threadIdx.x % 32, ty = threadIdx.x / 32;
    #pragma unroll
    for (int i = 0; i < 32; i += 8)
        t[ty + i][tx] = W[(size_t)(k0 + ty + i) * N + n0 + tx];
    __syncthreads();
    #pragma unroll
    for (int i = 0; i < 32; i += 8) {
        Bt[(size_t)(n0 + ty + i) * K + k0 + tx] = __float2half_rn(t[tx][ty + i]);
    }
}

// ---------------- SELU --------------------------------------------------------
__device__ __forceinline__ float selu_f(float v) {
    const float scale = 1.0507009873554805f;
    const float alpha = 1.6732632423543772f;
    return v > 0.f ? scale * v : scale * alpha * (expf(v) - 1.f);
}

// ================= mma.sync fp16 GEMM, cp.async double-buffered ===============
// C[M,N] = act(A @ Bt^T + bias). A=[M,K] fp16, Bt=[N,K] fp16, fp32 accum.
// F16OUT: write C as fp16 (feeds next GEMM); else fp32 to Cf.
template <int BM, int BN, int KTOT, int WM, int WN, int MINCTA,
          bool ACT, bool F16OUT>
__global__ void __launch_bounds__(256, MINCTA) mma_gemm(
    const __half* __restrict__ Ah, const __half* __restrict__ Bh,
    const float* __restrict__ bias,
    float* __restrict__ Cf, __half* __restrict__ Ch, int Ntot)
{
    constexpr int KC  = 64;          // K elements per smem stage
    constexpr int RB  = 128;         // bytes per smem row (KC * 2)
    constexpr int WGM = BM / WM;     // warps along M
    constexpr int MT  = WM / 16;
    constexpr int NT  = WN / 8;
    constexpr int STAGE = (BM + BN) * RB;
    static_assert((BM / WM) * (BN / WN) == 8, "8 warps");
    static_assert(NT % 2 == 0, "B ldmatrix.x4 covers 2 n-tiles");

    extern __shared__ char dsm[];
    uint32_t raw = smem_u32(dsm);
    uint32_t sb  = (raw + 1023u) & ~1023u;
    char* base   = dsm + (sb - raw);

    float* biass = (float*)base;     // [BN] floats in first 1024B
    uint32_t AHIa[2], BHIa[2];
    #pragma unroll
    for (int s = 0; s < 2; ++s) {
        uint32_t b0 = sb + 1024 + s * STAGE;
        AHIa[s] = b0;
        BHIa[s] = b0 + BM * RB;
    }

    const int tid  = threadIdx.x;
    const int wid  = tid >> 5;
    const int lane = tid & 31;
    const int bm0  = blockIdx.y * BM;
    const int bn0  = blockIdx.x * BN;
    const int wm0  = (wid % WGM) * WM;
    const int wn0  = (wid / WGM) * WN;

    for (int i = tid; i < BN; i += 256) biass[i] = bias[bn0 + i];

    float acc[MT][NT][4];
    #pragma unroll
    for (int i = 0; i < MT; ++i)
        #pragma unroll
        for (int j = 0; j < NT; ++j)
            #pragma unroll
            for (int q = 0; q < 4; ++q) acc[i][j][q] = 0.f;

    constexpr int A_IT = BM * 8 / 256;
    constexpr int B_IT = BN * 8 / 256;

    auto load_stage = [&](int kcc, int s) {
        const int kel = kcc * KC;
        #pragma unroll
        for (int i = 0; i < A_IT; ++i) {
            int e = tid + i * 256;
            int row = e >> 3, seg = e & 7;
            uint32_t so = SW128((uint32_t)(row * RB + seg * 16));
            size_t ga = (size_t)(bm0 + row) * KTOT + kel + seg * 8;
            cp16(AHIa[s] + so, Ah + ga);
        }
        #pragma unroll
        for (int i = 0; i < B_IT; ++i) {
            int e = tid + i * 256;
            int row = e >> 3, seg = e & 7;
            uint32_t so = SW128((uint32_t)(row * RB + seg * 16));
            size_t gb = (size_t)(bn0 + row) * KTOT + kel + seg * 8;
            cp16(BHIa[s] + so, Bh + gb);
        }
        cp_commit();
    };

    const int g  = lane >> 3;
    const int lr = lane & 7;
    const uint32_t a_row_off = (uint32_t)(wm0 + (g & 1) * 8 + lr) * RB + (uint32_t)(g >> 1) * 16;
    const uint32_t b_row_off = (uint32_t)(wn0 + (g >> 1) * 8 + lr) * RB + (uint32_t)(g & 1) * 16;

    constexpr int NCH = KTOT / KC;
    load_stage(0, 0);

    for (int kc = 0; kc < NCH; ++kc) {
        const int buf = kc & 1;
        if (kc + 1 < NCH) {
            load_stage(kc + 1, buf ^ 1);
            cp_wait<1>();
        } else {
            cp_wait<0>();
        }
        __syncthreads();

        const uint32_t AHIb = AHIa[buf], BHIb = BHIa[buf];

        #pragma unroll
        for (int ks = 0; ks < 4; ++ks) {
            const uint32_t kb = (uint32_t)ks * 32;

            uint32_t a_hi[MT][4];
            #pragma unroll
            for (int mt = 0; mt < MT; ++mt)
                ldsm_x4(a_hi[mt], AHIb + SW128(a_row_off + (uint32_t)mt * 16 * RB + kb));
            uint32_t b_hi[NT][2];
            #pragma unroll
            for (int np = 0; np < NT / 2; ++np) {
                uint32_t th[4];
                ldsm_x4(th, BHIb + SW128(b_row_off + (uint32_t)np * 16 * RB + kb));
                b_hi[np * 2][0] = th[0]; b_hi[np * 2][1] = th[1];
                b_hi[np * 2 + 1][0] = th[2]; b_hi[np * 2 + 1][1] = th[3];
            }
            #pragma unroll
            for (int mt = 0; mt < MT; ++mt)
                #pragma unroll
                for (int nt = 0; nt < NT; ++nt)
                    mma_f16(acc[mt][nt], a_hi[mt], b_hi[nt]);
        }
        __syncthreads();
    }

    // ---- epilogue: bias + act, write out ----
    const int er = lane >> 2;
    const int ec = (lane & 3) * 2;
    #pragma unroll
    for (int mt = 0; mt < MT; ++mt) {
        #pragma unroll
        for (int nt = 0; nt < NT; ++nt) {
            int col = wn0 + nt * 8 + ec;
            float bx = biass[col], by = biass[col + 1];
            float v0 = acc[mt][nt][0] + bx, v1 = acc[mt][nt][1] + by;
            float v2 = acc[mt][nt][2] + bx, v3 = acc[mt][nt][3] + by;
            if (ACT) { v0 = selu_f(v0); v1 = selu_f(v1); v2 = selu_f(v2); v3 = selu_f(v3); }
            size_t r0 = (size_t)(bm0 + wm0 + mt * 16 + er);
            size_t r1 = r0 + 8;
            size_t o0 = r0 * Ntot + bn0 + col;
            size_t o1 = r1 * Ntot + bn0 + col;
            if (F16OUT) {
                *reinterpret_cast<__half2*>(&Ch[o0]) =
                    __halves2half2(__float2half_rn(v0), __float2half_rn(v1));
                *reinterpret_cast<__half2*>(&Ch[o1]) =
                    __halves2half2(__float2half_rn(v2), __float2half_rn(v3));
            } else {
                *reinterpret_cast<float2*>(&Cf[o0]) = make_float2(v0, v1);
                *reinterpret_cast<float2*>(&Cf[o1]) = make_float2(v2, v3);
            }
        }
    }
}

// ---------------- launch ------------------------------------------------------
extern "C" void kernel_launch(void* const* d_in, const int* in_sizes, int n_in,
                              void* d_out, int out_size)
{
    const float* x     = (const float*)d_in[0];
    // d_in[1] = edge_index (unused), d_in[2] = edge_attr (unused)
    const float* u     = (const float*)d_in[3];
    const int*   batch = (const int*)d_in[4];
    const float* W1    = (const float*)d_in[5];
    const float* b1    = (const float*)d_in[6];
    const float* W2    = (const float*)d_in[7];
    const float* b2    = (const float*)d_in[8];
    float*       out   = (float*)d_out;

    const int n_nodes = in_sizes[0] / NODE_SIZE;

    void *p_a, *p_h, *p_w1, *p_w2;
    cudaGetSymbolAddress(&p_a,  g_a);
    cudaGetSymbolAddress(&p_h,  g_h);
    cudaGetSymbolAddress(&p_w1, g_w1t);
    cudaGetSymbolAddress(&p_w2, g_w2t);

    // GEMM1 (128x128): smem = 1024 + 2*(128+128)*128 = 66560 -> 2 CTAs/SM
    // GEMM2 (64x64):   smem = 1024 + 2*(64+64)*128   = 33792 -> 3 CTAs/SM
    constexpr int SMB1 = 1024 + 2 * (128 + 128) * 128;
    constexpr int SMB2 = 1024 + 2 * (64 + 64) * 128;
    cudaFuncSetAttribute(
        (const void*)mma_gemm<128, 128, INPUT_SIZE, 64, 32, 2, true, true>,
        cudaFuncAttributeMaxDynamicSharedMemorySize, SMB1);
    cudaFuncSetAttribute(
        (const void*)mma_gemm<64, 64, HIDDEN_SIZE, 16, 32, 3, false, false>,
        cudaFuncAttributeMaxDynamicSharedMemorySize, SMB2);

    // weight transpose to fp16 (small)
    wsplit<<<dim3(INPUT_SIZE / 32, HIDDEN_SIZE / 32), 256>>>(
        W1, (__half*)p_w1, INPUT_SIZE, HIDDEN_SIZE);
    wsplit<<<dim3(HIDDEN_SIZE / 32, GLOBAL_SIZE / 32), 256>>>(
        W2, (__half*)p_w2, HIDDEN_SIZE, GLOBAL_SIZE);

    // fused segment-mean + concat (the HBM-bound pass over x)
    mean_split<<<N_GRAPHS, 128>>>(x, batch, u, n_nodes);

    // GEMM1: [4096,768] @ [768,1024] + b1, SELU -> g_h (fp16)
    // 256 CTAs = one wave at 2 CTAs/SM; ldsm/MMA = 0.375
    mma_gemm<128, 128, INPUT_SIZE, 64, 32, 2, true, true>
        <<<dim3(HIDDEN_SIZE / 128, N_GRAPHS / 128), 256, SMB1>>>(
            (const __half*)p_a, (const __half*)p_w1,
            b1, nullptr, (__half*)p_h, HIDDEN_SIZE);

    // GEMM2: [4096,1024] @ [1024,256] + b2 -> out (fp32), 256 CTAs = one wave
    mma_gemm<64, 64, HIDDEN_SIZE, 16, 32, 3, false, false>
        <<<dim3(GLOBAL_SIZE / 64, N_GRAPHS / 64), 256, SMB2>>>(
            (const __half*)p_h, (const __half*)p_w2,
            b2, out, nullptr, GLOBAL_SIZE);
}